// round 1
// baseline (speedup 1.0000x reference)
#include <cuda_runtime.h>
#include <cuda_bf16.h>
#include <math.h>

// Problem constants
#define NB 32     // batch (both visual and textual)
#define NP 192    // patches
#define NA 30     // attributes
#define NE 256    // embed dim
#define NK 768    // input feature dim
#define SV 193    // visual seq len (1 + P)
#define ST 31     // textual seq len (1 + A)

#define VE_OFF 0
#define TE_OFF 8192
#define PM_OFF 16384
#define AM_OFF 24576
#define SIM_OFF 32768

// Scratch (device globals; no allocation allowed)
__device__ float g_patch[NB * NP * NE];   // [32,192,256]
__device__ float g_att[NB * NA * NE];     // [32,30,256]
__device__ float g_rp[NB * NP];           // inverse L2 norms of patch rows
__device__ float g_ra[NB * NA];           // inverse L2 norms of att rows

// ---------------------------------------------------------------------------
// Generic projection GEMM: out[m][n] = sum_k X[row(m)][k] * W[n][k] + bias[n]
// row(m) token index = (m/gs)*S + off + m%gs  (handles cls/patch/att slicing)
// N = 256 fixed, K = 768 fixed. 64x64 tile, 256 threads, 4x4 microtile.
// ---------------------------------------------------------------------------
__global__ __launch_bounds__(256) void proj_kernel(
    const float* __restrict__ X, const float* __restrict__ W,
    const float* __restrict__ bias, float* __restrict__ out,
    int M, int S, int gs, int off)
{
    __shared__ float As[64][20];   // [m][k], padded
    __shared__ float Bs[16][68];   // [k][n], padded

    const int tid = threadIdx.x;
    const int col0 = blockIdx.x * 64;
    const int row0 = blockIdx.y * 64;
    const int tm = tid >> 4;       // 0..15
    const int tn = tid & 15;       // 0..15

    float c[4][4];
#pragma unroll
    for (int i = 0; i < 4; i++)
#pragma unroll
        for (int j = 0; j < 4; j++) c[i][j] = 0.f;

    const int lm = tid >> 2;          // 0..63 : row (A) / col (B) to load
    const int lk = (tid & 3) << 2;    // 0,4,8,12
    const int grow = row0 + lm;
    const bool rowok = (grow < M);
    size_t srcrow = 0;
    if (rowok) srcrow = (size_t)((grow / gs) * S + off + grow % gs) * NK;
    const size_t wrow = (size_t)(col0 + lm) * NK;

    for (int k0 = 0; k0 < NK; k0 += 16) {
        float4 av = make_float4(0.f, 0.f, 0.f, 0.f);
        if (rowok) av = *(const float4*)&X[srcrow + k0 + lk];
        *(float4*)&As[lm][lk] = av;
        float4 bv = *(const float4*)&W[wrow + k0 + lk];
        Bs[lk + 0][lm] = bv.x;
        Bs[lk + 1][lm] = bv.y;
        Bs[lk + 2][lm] = bv.z;
        Bs[lk + 3][lm] = bv.w;
        __syncthreads();

#pragma unroll
        for (int k = 0; k < 16; k++) {
            float a0 = As[tm * 4 + 0][k];
            float a1 = As[tm * 4 + 1][k];
            float a2 = As[tm * 4 + 2][k];
            float a3 = As[tm * 4 + 3][k];
            float4 b4 = *(float4*)&Bs[k][tn * 4];
            c[0][0] = fmaf(a0, b4.x, c[0][0]); c[0][1] = fmaf(a0, b4.y, c[0][1]);
            c[0][2] = fmaf(a0, b4.z, c[0][2]); c[0][3] = fmaf(a0, b4.w, c[0][3]);
            c[1][0] = fmaf(a1, b4.x, c[1][0]); c[1][1] = fmaf(a1, b4.y, c[1][1]);
            c[1][2] = fmaf(a1, b4.z, c[1][2]); c[1][3] = fmaf(a1, b4.w, c[1][3]);
            c[2][0] = fmaf(a2, b4.x, c[2][0]); c[2][1] = fmaf(a2, b4.y, c[2][1]);
            c[2][2] = fmaf(a2, b4.z, c[2][2]); c[2][3] = fmaf(a2, b4.w, c[2][3]);
            c[3][0] = fmaf(a3, b4.x, c[3][0]); c[3][1] = fmaf(a3, b4.y, c[3][1]);
            c[3][2] = fmaf(a3, b4.z, c[3][2]); c[3][3] = fmaf(a3, b4.w, c[3][3]);
        }
        __syncthreads();
    }

    const float4 b4 = *(const float4*)&bias[col0 + tn * 4];
#pragma unroll
    for (int i = 0; i < 4; i++) {
        int r = row0 + tm * 4 + i;
        if (r < M) {
            float4 o;
            o.x = c[i][0] + b4.x; o.y = c[i][1] + b4.y;
            o.z = c[i][2] + b4.z; o.w = c[i][3] + b4.w;
            *(float4*)&out[(size_t)r * NE + col0 + tn * 4] = o;
        }
    }
}

// ---------------------------------------------------------------------------
// Inverse L2 norms of all patch rows (6144) and att rows (960). Warp per row.
// rn = 1/max(||x||, 1e-12)  implemented as rsqrt(max(ss, 1e-24))
// ---------------------------------------------------------------------------
__global__ __launch_bounds__(256) void norm_kernel()
{
    const int w = (blockIdx.x * blockDim.x + threadIdx.x) >> 5;
    const int lane = threadIdx.x & 31;
    if (w >= NB * NP + NB * NA) return;
    const float* row;
    float* dst;
    if (w < NB * NP) { row = g_patch + (size_t)w * NE; dst = &g_rp[w]; }
    else            { row = g_att + (size_t)(w - NB * NP) * NE; dst = &g_ra[w - NB * NP]; }
    float4 x0 = *(const float4*)&row[lane * 4];
    float4 x1 = *(const float4*)&row[128 + lane * 4];
    float ss = x0.x * x0.x + x0.y * x0.y + x0.z * x0.z + x0.w * x0.w
             + x1.x * x1.x + x1.y * x1.y + x1.z * x1.z + x1.w * x1.w;
#pragma unroll
    for (int o = 16; o > 0; o >>= 1) ss += __shfl_xor_sync(~0u, ss, o);
    if (lane == 0) *dst = rsqrtf(fmaxf(ss, 1e-24f));
}

// ---------------------------------------------------------------------------
// patch_mean and att_mean. Grid 32 blocks x 256 threads (b, e).
// ---------------------------------------------------------------------------
__global__ __launch_bounds__(256) void mean_kernel(const int* __restrict__ att_nums,
                                                   float* __restrict__ out)
{
    const int b = blockIdx.x;
    const int e = threadIdx.x;
    float pm = 0.f;
    const float* pb = g_patch + (size_t)b * NP * NE + e;
#pragma unroll 4
    for (int p = 0; p < NP; p++) pm += pb[(size_t)p * NE];
    out[PM_OFF + b * NE + e] = pm / (float)NP;

    float am = 0.f;
    const float* ab = g_att + (size_t)b * NA * NE + e;
#pragma unroll
    for (int a = 0; a < NA; a++) am += ab[(size_t)a * NE];
    out[AM_OFF + b * NE + e] = am / (float)att_nums[b];
}

// ---------------------------------------------------------------------------
// Fused per-(t,v)-pair kernel. blockIdx.x = v, blockIdx.y = t. 256 threads.
// Computes D (shared dot matrix), both softmaxes, attend_patch -> V vec,
// attend_att rows on-the-fly -> U vec, sim = dot(U,V)/(an*30).
// ---------------------------------------------------------------------------
__global__ __launch_bounds__(256) void pair_kernel(const int* __restrict__ mask,
                                                   const int* __restrict__ att_nums,
                                                   float* __restrict__ out_sim)
{
    extern __shared__ float sm[];
    float* s_att  = sm;              // 7680  : att[t] raw [30][256]
    float* s_D    = sm + 7680;       // 5760  : D [30][192], later attn2
    float* s_reg  = sm + 13440;      // 13440 : union region
    float* s_attn1 = s_reg;          //   5760 : attn1 [30][192]
    float* s_ap    = s_reg + 5760;   //   7680 : attend_patch [30][256]
    float* s_tile  = s_reg;          //   13056: stage-A patch tile [192][68]
    float* s_red  = sm + 26880;      // 32 : per-warp partials (8 warps x 4)
    float* s_red2 = sm + 26912;      // 8
    float* s_ra   = sm + 26920;      // 30
    float* s_rp   = sm + 26950;      // 192
    float* s_apn  = sm + 27142;      // 30
    float* s_padf = sm + 27172;      // 30
    float* s_an   = sm + 27202;      // 1
    // total: 27203 floats = 108812 B

    const int v = blockIdx.x, t = blockIdx.y;
    const int tid = threadIdx.x;
    const int lane = tid & 31, wid = tid >> 5;

    // ---- preload ----
    const float* attp = g_att + (size_t)t * NA * NE;
    for (int i = tid; i < NA * NE; i += 256) s_att[i] = attp[i];
    if (tid < NA) {
        s_ra[tid] = g_ra[t * NA + tid];
        s_padf[tid] = (mask[t * NA + tid] != 0) ? 1.f : 0.f;
    }
    if (tid < NP) s_rp[tid] = g_rp[v * NP + tid];
    if (tid == 0) s_an[0] = (float)att_nums[t];
    __syncthreads();

    const float* pbase = g_patch + (size_t)v * NP * NE;

    // ---- Stage A: D[a][p] = relu(raw_dot * ra * rp) * 20 ----
    float acc[NA];
#pragma unroll
    for (int a = 0; a < NA; a++) acc[a] = 0.f;

    for (int ec = 0; ec < 4; ec++) {
        const int e0 = ec * 64;
        // cooperative coalesced tile load: [192][64] -> s_tile[p*68 + c]
        for (int q = tid; q < NP * 16; q += 256) {
            int p = q >> 4, c4 = (q & 15) << 2;
            float4 w = *(const float4*)&pbase[(size_t)p * NE + e0 + c4];
            *(float4*)&s_tile[p * 68 + c4] = w;
        }
        __syncthreads();
        if (tid < NP) {
            const int p = tid;
#pragma unroll 1
            for (int k = 0; k < 64; k += 4) {
                float4 pf = *(float4*)&s_tile[p * 68 + k];
#pragma unroll
                for (int a = 0; a < NA; a++) {
                    float4 af = *(float4*)&s_att[a * NE + e0 + k];
                    acc[a] = fmaf(af.x, pf.x, fmaf(af.y, pf.y,
                             fmaf(af.z, pf.z, fmaf(af.w, pf.w, acc[a]))));
                }
            }
        }
        __syncthreads();
    }
    if (tid < NP) {
        const float rp = s_rp[tid];
#pragma unroll
        for (int a = 0; a < NA; a++) {
            float d = acc[a] * s_ra[a] * rp;
            d = fmaxf(d, 0.f) * 20.f;
            s_D[a * NP + tid] = d;
        }
    }
    __syncthreads();

    // ---- Stage B: attn1 = softmax over p of each a-row ----
    for (int r = wid; r < NA; r += 8) {
        float xv[6];
        float m = -1e30f;
#pragma unroll
        for (int j = 0; j < 6; j++) {
            xv[j] = s_D[r * NP + lane + j * 32];
            m = fmaxf(m, xv[j]);
        }
#pragma unroll
        for (int o = 16; o > 0; o >>= 1) m = fmaxf(m, __shfl_xor_sync(~0u, m, o));
        float s = 0.f;
#pragma unroll
        for (int j = 0; j < 6; j++) { xv[j] = expf(xv[j] - m); s += xv[j]; }
#pragma unroll
        for (int o = 16; o > 0; o >>= 1) s += __shfl_xor_sync(~0u, s, o);
        const float rinv = 1.f / s;
#pragma unroll
        for (int j = 0; j < 6; j++) s_attn1[r * NP + lane + j * 32] = xv[j] * rinv;
    }
    __syncthreads();

    // ---- Stage C: attend_patch[a][e] = attn1 @ patch  (thread owns e) ----
    float acc2[NA];
#pragma unroll
    for (int a = 0; a < NA; a++) acc2[a] = 0.f;
    {
        const int e = tid;
#pragma unroll 1
        for (int p0 = 0; p0 < NP; p0 += 4) {
            float pv0 = __ldg(&pbase[(size_t)(p0 + 0) * NE + e]);
            float pv1 = __ldg(&pbase[(size_t)(p0 + 1) * NE + e]);
            float pv2 = __ldg(&pbase[(size_t)(p0 + 2) * NE + e]);
            float pv3 = __ldg(&pbase[(size_t)(p0 + 3) * NE + e]);
#pragma unroll
            for (int a = 0; a < NA; a++) {
                float4 q = *(float4*)&s_attn1[a * NP + p0];
                acc2[a] = fmaf(q.x, pv0, fmaf(q.y, pv1,
                          fmaf(q.z, pv2, fmaf(q.w, pv3, acc2[a]))));
            }
        }
#pragma unroll
        for (int a = 0; a < NA; a++) s_ap[a * NE + e] = acc2[a];
    }
    __syncthreads();

    // ap row inverse norms
    for (int r = wid; r < NA; r += 8) {
        float ss = 0.f;
#pragma unroll
        for (int j = 0; j < 2; j++) {
            float4 w = *(float4*)&s_ap[r * NE + lane * 4 + j * 128];
            ss += w.x * w.x + w.y * w.y + w.z * w.z + w.w * w.w;
        }
#pragma unroll
        for (int o = 16; o > 0; o >>= 1) ss += __shfl_xor_sync(~0u, ss, o);
        if (lane == 0) s_apn[r] = rsqrtf(fmaxf(ss, 1e-24f));
    }
    __syncthreads();

    // V[e] = sum_a l2norm(ap)[a][e] with padded rows zeroed  (kept in register)
    float v_e = 0.f;
#pragma unroll
    for (int a = 0; a < NA; a++) v_e += acc2[a] * s_apn[a] * (1.f - s_padf[a]);

    // ---- Stage E: attn2 = masked softmax over a, in place in s_D ----
    if (tid < NP) {
        const int p = tid;
        float val[NA];
        float m = -1e30f;
#pragma unroll
        for (int a = 0; a < NA; a++) {
            val[a] = (s_padf[a] > 0.5f) ? -1e9f : s_D[a * NP + p];
            m = fmaxf(m, val[a]);
        }
        float s = 0.f;
#pragma unroll
        for (int a = 0; a < NA; a++) { val[a] = expf(val[a] - m); s += val[a]; }
        const float rinv = 1.f / s;
#pragma unroll
        for (int a = 0; a < NA; a++) s_D[a * NP + p] = val[a] * rinv;
    }
    __syncthreads();

    // ---- Stage F: attend_att rows on the fly -> U[e] (register) ----
    float r_att[NA];
    {
        const int e = tid;
#pragma unroll
        for (int a = 0; a < NA; a++) r_att[a] = s_att[a * NE + e];
    }
    float u_e = 0.f;
#pragma unroll 1
    for (int p0 = 0; p0 < NP; p0 += 4) {
        float r0 = 0.f, r1 = 0.f, r2 = 0.f, r3 = 0.f;
#pragma unroll
        for (int a = 0; a < NA; a++) {
            float4 w = *(float4*)&s_D[a * NP + p0];   // broadcast across threads
            const float ra = r_att[a];
            r0 = fmaf(w.x, ra, r0);
            r1 = fmaf(w.y, ra, r1);
            r2 = fmaf(w.z, ra, r2);
            r3 = fmaf(w.w, ra, r3);
        }
        // cross-thread sumsq reduction for 4 rows
        float q0 = r0 * r0, q1 = r1 * r1, q2 = r2 * r2, q3 = r3 * r3;
#pragma unroll
        for (int o = 16; o > 0; o >>= 1) {
            q0 += __shfl_xor_sync(~0u, q0, o);
            q1 += __shfl_xor_sync(~0u, q1, o);
            q2 += __shfl_xor_sync(~0u, q2, o);
            q3 += __shfl_xor_sync(~0u, q3, o);
        }
        if (lane == 0) *(float4*)&s_red[wid * 4] = make_float4(q0, q1, q2, q3);
        __syncthreads();
        float t0 = 0.f, t1 = 0.f, t2 = 0.f, t3 = 0.f;
#pragma unroll
        for (int w2 = 0; w2 < 8; w2++) {
            float4 pr = *(float4*)&s_red[w2 * 4];
            t0 += pr.x; t1 += pr.y; t2 += pr.z; t3 += pr.w;
        }
        u_e = fmaf(r0, rsqrtf(fmaxf(t0, 1e-24f)), u_e);
        u_e = fmaf(r1, rsqrtf(fmaxf(t1, 1e-24f)), u_e);
        u_e = fmaf(r2, rsqrtf(fmaxf(t2, 1e-24f)), u_e);
        u_e = fmaf(r3, rsqrtf(fmaxf(t3, 1e-24f)), u_e);
        __syncthreads();   // protect s_red before next iteration's writes
    }

    // ---- Stage G: sim = dot(U, V) / (an * 30) ----
    float part = u_e * v_e;
#pragma unroll
    for (int o = 16; o > 0; o >>= 1) part += __shfl_xor_sync(~0u, part, o);
    if (lane == 0) s_red2[wid] = part;
    __syncthreads();
    if (tid == 0) {
        float tot = 0.f;
#pragma unroll
        for (int w2 = 0; w2 < 8; w2++) tot += s_red2[w2];
        out_sim[t * NB + v] = tot / (s_an[0] * (float)NA);
    }
}

// ---------------------------------------------------------------------------
extern "C" void kernel_launch(void* const* d_in, const int* in_sizes, int n_in,
                              void* d_out, int out_size)
{
    const float* vf      = (const float*)d_in[0];
    const float* tf      = (const float*)d_in[1];
    const int*   mask    = (const int*)d_in[2];
    const int*   att_num = (const int*)d_in[3];
    const float* W_vis   = (const float*)d_in[4];
    const float* b_vis   = (const float*)d_in[5];
    const float* W_txt   = (const float*)d_in[6];
    const float* b_txt   = (const float*)d_in[7];
    const float* W_patch = (const float*)d_in[8];
    const float* b_patch = (const float*)d_in[9];
    const float* W_att   = (const float*)d_in[10];
    const float* b_att   = (const float*)d_in[11];
    float* out = (float*)d_out;

    void* p_patch = nullptr;
    void* p_att = nullptr;
    cudaGetSymbolAddress(&p_patch, g_patch);
    cudaGetSymbolAddress(&p_att, g_att);

    dim3 blk(256);
    // projections
    proj_kernel<<<dim3(4, (NB * NP + 63) / 64), blk>>>(vf, W_patch, b_patch,
                                                       (float*)p_patch, NB * NP, SV, NP, 1);
    proj_kernel<<<dim3(4, (NB * NA + 63) / 64), blk>>>(tf, W_att, b_att,
                                                       (float*)p_att, NB * NA, ST, NA, 1);
    proj_kernel<<<dim3(4, 1), blk>>>(vf, W_vis, b_vis, out + VE_OFF, NB, SV, 1, 0);
    proj_kernel<<<dim3(4, 1), blk>>>(tf, W_txt, b_txt, out + TE_OFF, NB, ST, 1, 0);

    // row norms (6144 + 960 rows, warp per row)
    {
        int nrows = NB * NP + NB * NA;
        int nwarps_per_blk = 8;
        int nblk = (nrows + nwarps_per_blk - 1) / nwarps_per_blk;
        norm_kernel<<<nblk, blk>>>();
    }

    // means
    mean_kernel<<<NB, blk>>>(att_num, out);

    // fused pair kernel
    const int smem_bytes = 27203 * 4;
    cudaFuncSetAttribute(pair_kernel, cudaFuncAttributeMaxDynamicSharedMemorySize,
                         smem_bytes);
    pair_kernel<<<dim3(NB, NB), blk, smem_bytes>>>(mask, att_num, out + SIM_OFF);
}

// round 2
// speedup vs baseline: 1.4301x; 1.4301x over previous
#include <cuda_runtime.h>
#include <math.h>

// Problem constants
#define NB 32     // batch
#define NP 192    // patches
#define NA 30     // attributes
#define NE 256    // embed dim
#define NK 768    // input feature dim
#define SV 193    // visual seq len
#define ST 31     // textual seq len

#define VE_OFF 0
#define TE_OFF 8192
#define PM_OFF 16384
#define AM_OFF 24576
#define SIM_OFF 32768

// Scratch
__device__ float g_patch[NB * NP * NE];
__device__ float g_att[NB * NA * NE];
__device__ float g_rp[NB * NP];
__device__ float g_ra[NB * NA];
__device__ float g_G[NB * NA * 32];     // Gram of att rows per t, row stride 32

typedef unsigned long long ull;

__device__ __forceinline__ void fma2(ull& d, ull a, ull b) {
    asm("fma.rn.f32x2 %0, %1, %2, %3;" : "=l"(d) : "l"(a), "l"(b), "l"(d));
}
__device__ __forceinline__ ull pk2(float x, float y) {
    ull r; asm("mov.b64 %0, {%1,%2};" : "=l"(r) : "f"(x), "f"(y)); return r;
}
__device__ __forceinline__ float2 upk(ull v) {
    float2 r; asm("mov.b64 {%0,%1}, %2;" : "=f"(r.x), "=f"(r.y) : "l"(v)); return r;
}

// ---------------------------------------------------------------------------
// Projection GEMM (patch / att): out[m][n] = X[row(m)]·W[n] + bias[n]
// ---------------------------------------------------------------------------
__global__ __launch_bounds__(256) void proj_kernel(
    const float* __restrict__ X, const float* __restrict__ W,
    const float* __restrict__ bias, float* __restrict__ out,
    int M, int S, int gs, int off)
{
    __shared__ float As[64][20];
    __shared__ float Bs[16][68];

    const int tid = threadIdx.x;
    const int col0 = blockIdx.x * 64;
    const int row0 = blockIdx.y * 64;
    const int tm = tid >> 4;
    const int tn = tid & 15;

    float c[4][4];
#pragma unroll
    for (int i = 0; i < 4; i++)
#pragma unroll
        for (int j = 0; j < 4; j++) c[i][j] = 0.f;

    const int lm = tid >> 2;
    const int lk = (tid & 3) << 2;
    const int grow = row0 + lm;
    const bool rowok = (grow < M);
    size_t srcrow = 0;
    if (rowok) srcrow = (size_t)((grow / gs) * S + off + grow % gs) * NK;
    const size_t wrow = (size_t)(col0 + lm) * NK;

    for (int k0 = 0; k0 < NK; k0 += 16) {
        float4 av = make_float4(0.f, 0.f, 0.f, 0.f);
        if (rowok) av = *(const float4*)&X[srcrow + k0 + lk];
        *(float4*)&As[lm][lk] = av;
        float4 bv = *(const float4*)&W[wrow + k0 + lk];
        Bs[lk + 0][lm] = bv.x;
        Bs[lk + 1][lm] = bv.y;
        Bs[lk + 2][lm] = bv.z;
        Bs[lk + 3][lm] = bv.w;
        __syncthreads();

#pragma unroll
        for (int k = 0; k < 16; k++) {
            float a0 = As[tm * 4 + 0][k];
            float a1 = As[tm * 4 + 1][k];
            float a2 = As[tm * 4 + 2][k];
            float a3 = As[tm * 4 + 3][k];
            float4 b4 = *(float4*)&Bs[k][tn * 4];
            c[0][0] = fmaf(a0, b4.x, c[0][0]); c[0][1] = fmaf(a0, b4.y, c[0][1]);
            c[0][2] = fmaf(a0, b4.z, c[0][2]); c[0][3] = fmaf(a0, b4.w, c[0][3]);
            c[1][0] = fmaf(a1, b4.x, c[1][0]); c[1][1] = fmaf(a1, b4.y, c[1][1]);
            c[1][2] = fmaf(a1, b4.z, c[1][2]); c[1][3] = fmaf(a1, b4.w, c[1][3]);
            c[2][0] = fmaf(a2, b4.x, c[2][0]); c[2][1] = fmaf(a2, b4.y, c[2][1]);
            c[2][2] = fmaf(a2, b4.z, c[2][2]); c[2][3] = fmaf(a2, b4.w, c[2][3]);
            c[3][0] = fmaf(a3, b4.x, c[3][0]); c[3][1] = fmaf(a3, b4.y, c[3][1]);
            c[3][2] = fmaf(a3, b4.z, c[3][2]); c[3][3] = fmaf(a3, b4.w, c[3][3]);
        }
        __syncthreads();
    }

    const float4 b4 = *(const float4*)&bias[col0 + tn * 4];
#pragma unroll
    for (int i = 0; i < 4; i++) {
        int r = row0 + tm * 4 + i;
        if (r < M) {
            float4 o;
            o.x = c[i][0] + b4.x; o.y = c[i][1] + b4.y;
            o.z = c[i][2] + b4.z; o.w = c[i][3] + b4.w;
            *(float4*)&out[(size_t)r * NE + col0 + tn * 4] = o;
        }
    }
}

// ---------------------------------------------------------------------------
// cls projections (visual_embed + textual_embed), warp per output dot
// ---------------------------------------------------------------------------
__global__ __launch_bounds__(256) void cls_kernel(
    const float* __restrict__ vf, const float* __restrict__ tf,
    const float* __restrict__ Wv, const float* __restrict__ bv,
    const float* __restrict__ Wt, const float* __restrict__ bt,
    float* __restrict__ out)
{
    const int wg = (blockIdx.x * 256 + threadIdx.x) >> 5;
    const int lane = threadIdx.x & 31;
    const int half = wg >> 13;        // 0=vis, 1=txt
    const int o = wg & 8191;
    const int b = o >> 8, n = o & 255;
    const float* X = half ? (tf + (size_t)b * ST * NK) : (vf + (size_t)b * SV * NK);
    const float* W = (half ? Wt : Wv) + (size_t)n * NK;
    float acc = 0.f;
#pragma unroll
    for (int j = 0; j < 6; j++) {
        float4 x = *(const float4*)&X[lane * 4 + j * 128];
        float4 w = *(const float4*)&W[lane * 4 + j * 128];
        acc += x.x * w.x + x.y * w.y + x.z * w.z + x.w * w.w;
    }
#pragma unroll
    for (int off = 16; off > 0; off >>= 1) acc += __shfl_xor_sync(~0u, acc, off);
    if (lane == 0)
        out[(half ? TE_OFF : VE_OFF) + b * NE + n] = acc + (half ? bt : bv)[n];
}

// ---------------------------------------------------------------------------
// Inverse L2 norms of patch rows and att rows. Warp per row.
// ---------------------------------------------------------------------------
__global__ __launch_bounds__(256) void norm_kernel()
{
    const int w = (blockIdx.x * blockDim.x + threadIdx.x) >> 5;
    const int lane = threadIdx.x & 31;
    if (w >= NB * NP + NB * NA) return;
    const float* row;
    float* dst;
    if (w < NB * NP) { row = g_patch + (size_t)w * NE; dst = &g_rp[w]; }
    else            { row = g_att + (size_t)(w - NB * NP) * NE; dst = &g_ra[w - NB * NP]; }
    float4 x0 = *(const float4*)&row[lane * 4];
    float4 x1 = *(const float4*)&row[128 + lane * 4];
    float ss = x0.x * x0.x + x0.y * x0.y + x0.z * x0.z + x0.w * x0.w
             + x1.x * x1.x + x1.y * x1.y + x1.z * x1.z + x1.w * x1.w;
#pragma unroll
    for (int o = 16; o > 0; o >>= 1) ss += __shfl_xor_sync(~0u, ss, o);
    if (lane == 0) *dst = rsqrtf(fmaxf(ss, 1e-24f));
}

// ---------------------------------------------------------------------------
// Gram matrix G[t][a][b] = att_a . att_b  (raw, unnormalized). Block per t.
// ---------------------------------------------------------------------------
__global__ __launch_bounds__(256) void gram_kernel()
{
    __shared__ float s[NA * NE];
    const int t = blockIdx.x, tid = threadIdx.x;
    const float* ap = g_att + (size_t)t * NA * NE;
    for (int i = tid; i < NA * NE; i += 256) s[i] = ap[i];
    __syncthreads();
    for (int idx = tid; idx < NA * NA; idx += 256) {
        int a = idx / NA, b = idx % NA;
        const float* ra = s + a * NE;
        const float* rb = s + b * NE;
        float acc = 0.f;
#pragma unroll 4
        for (int e = 0; e < NE; e += 4) {
            float4 x = *(float4*)&ra[e];
            float4 y = *(float4*)&rb[e];
            acc += x.x * y.x + x.y * y.y + x.z * y.z + x.w * y.w;
        }
        g_G[t * NA * 32 + a * 32 + b] = acc;
    }
}

// ---------------------------------------------------------------------------
// patch_mean and att_mean
// ---------------------------------------------------------------------------
__global__ __launch_bounds__(256) void mean_kernel(const int* __restrict__ att_nums,
                                                   float* __restrict__ out)
{
    const int b = blockIdx.x;
    const int e = threadIdx.x;
    float pm = 0.f;
    const float* pb = g_patch + (size_t)b * NP * NE + e;
#pragma unroll 4
    for (int p = 0; p < NP; p++) pm += pb[(size_t)p * NE];
    out[PM_OFF + b * NE + e] = pm / (float)NP;

    float am = 0.f;
    const float* ab = g_att + (size_t)b * NA * NE + e;
#pragma unroll
    for (int a = 0; a < NA; a++) am += ab[(size_t)a * NE];
    out[AM_OFF + b * NE + e] = am / (float)att_nums[b];
}

// ---------------------------------------------------------------------------
// Pair kernel smem layout (floats)
// ---------------------------------------------------------------------------
#define OFF_M    0
#define OFF_A1   5760
#define OFF_ATT  11520
#define OFF_A2   11520        /* aliases s_att (dead after stage A) */
#define OFF_TILE 19200
#define TILE_LD  36
#define OFF_G    26112
#define OFF_RA   27072
#define OFF_RP   27104
#define OFF_PADF 27296
#define OFF_W    27328
#define OFF_W2   27520
#define OFF_C    27552
#define OFF_RED  27584
#define OFF_AN   27648
#define SMEM_F   27652

// Stage C: sum-of-squares of attend_patch rows (a0..a0+NAq-1), f32x2 over e.
// Thread owns 4 consecutive e's (e4), h selects a-range. Writes per-warp
// partials into s_red[warp*8 + a].
template<int NAq>
__device__ __forceinline__ void stage_c(const float* __restrict__ pbase,
                                        const float* __restrict__ s_A1,
                                        float* __restrict__ s_red,
                                        int e4, int h)
{
    ull acc[NAq][2];
#pragma unroll
    for (int a = 0; a < NAq; a++) { acc[a][0] = 0ull; acc[a][1] = 0ull; }
    const int a0 = h * 8;
#pragma unroll 1
    for (int p0 = 0; p0 < NP; p0 += 4) {
        ulonglong2 u0 = *(const ulonglong2*)&pbase[(size_t)(p0 + 0) * NE + e4 * 4];
        ulonglong2 u1 = *(const ulonglong2*)&pbase[(size_t)(p0 + 1) * NE + e4 * 4];
        ulonglong2 u2 = *(const ulonglong2*)&pbase[(size_t)(p0 + 2) * NE + e4 * 4];
        ulonglong2 u3 = *(const ulonglong2*)&pbase[(size_t)(p0 + 3) * NE + e4 * 4];
#pragma unroll
        for (int a = 0; a < NAq; a++) {
            float4 q = *(const float4*)&s_A1[(a0 + a) * NP + p0];
            ull w0 = pk2(q.x, q.x), w1 = pk2(q.y, q.y);
            ull w2 = pk2(q.z, q.z), w3 = pk2(q.w, q.w);
            fma2(acc[a][0], w0, u0.x); fma2(acc[a][1], w0, u0.y);
            fma2(acc[a][0], w1, u1.x); fma2(acc[a][1], w1, u1.y);
            fma2(acc[a][0], w2, u2.x); fma2(acc[a][1], w2, u2.y);
            fma2(acc[a][0], w3, u3.x); fma2(acc[a][1], w3, u3.y);
        }
    }
    const int lane = threadIdx.x & 31, warp = threadIdx.x >> 5;
#pragma unroll
    for (int a = 0; a < NAq; a++) {
        float2 f0 = upk(acc[a][0]), f1 = upk(acc[a][1]);
        float s = f0.x * f0.x + f0.y * f0.y + f1.x * f1.x + f1.y * f1.y;
#pragma unroll
        for (int o = 16; o > 0; o >>= 1) s += __shfl_xor_sync(~0u, s, o);
        if (lane == 0) s_red[warp * 8 + a] = s;
    }
}

// ---------------------------------------------------------------------------
// Fused per-(t,v) pair kernel. blockIdx.x = v, blockIdx.y = t. 256 threads.
// sim[t,v] = c^T M d / (an*30)
// ---------------------------------------------------------------------------
__global__ __launch_bounds__(256, 2) void pair_kernel(const int* __restrict__ mask,
                                                      const int* __restrict__ att_nums,
                                                      float* __restrict__ out_sim)
{
    extern __shared__ float sm[];
    const int v = blockIdx.x, t = blockIdx.y;
    const int tid = threadIdx.x, lane = tid & 31, wid = tid >> 5;

    float* s_M    = sm + OFF_M;
    float* s_A1   = sm + OFF_A1;
    float* s_att  = sm + OFF_ATT;
    float* s_A2   = sm + OFF_A2;
    float* s_tile = sm + OFF_TILE;
    float* s_G    = sm + OFF_G;
    float* s_ra   = sm + OFF_RA;
    float* s_rp   = sm + OFF_RP;
    float* s_padf = sm + OFF_PADF;
    float* s_w    = sm + OFF_W;
    float* s_w2   = sm + OFF_W2;
    float* s_c    = sm + OFF_C;
    float* s_red  = sm + OFF_RED;
    float* s_an   = sm + OFF_AN;

    // ---- preload ----
    const float* attp = g_att + (size_t)t * NA * NE;
    for (int i = tid; i < NA * NE; i += 256) s_att[i] = attp[i];
    const float* gGp = g_G + t * NA * 32;
    for (int i = tid; i < NA * 32; i += 256) s_G[i] = gGp[i];
    if (tid < NA) {
        s_ra[tid] = g_ra[t * NA + tid];
        s_padf[tid] = (mask[t * NA + tid] != 0) ? 1.f : 0.f;
    }
    if (tid < NP) s_rp[tid] = g_rp[v * NP + tid];
    if (tid == 0) s_an[0] = (float)att_nums[t];
    __syncthreads();

    const float* pbase = g_patch + (size_t)v * NP * NE;

    // ---- Stage A: M[a][p] = att_a . patch_p (raw), f32x2 over e ----
    ull acc[NA];
#pragma unroll
    for (int a = 0; a < NA; a++) acc[a] = 0ull;

    for (int ec = 0; ec < 8; ec++) {
        const int e0 = ec * 32;
        for (int q = tid; q < NP * 8; q += 256) {
            int p = q >> 3, c4 = (q & 7) << 2;
            *(float4*)&s_tile[p * TILE_LD + c4] =
                *(const float4*)&pbase[(size_t)p * NE + e0 + c4];
        }
        __syncthreads();
        if (tid < NP) {
#pragma unroll
            for (int c4 = 0; c4 < 32; c4 += 4) {
                ulonglong2 pf = *(const ulonglong2*)&s_tile[tid * TILE_LD + c4];
#pragma unroll
                for (int a = 0; a < NA; a++) {
                    ulonglong2 af = *(const ulonglong2*)&s_att[a * NE + e0 + c4];
                    fma2(acc[a], af.x, pf.x);
                    fma2(acc[a], af.y, pf.y);
                }
            }
        }
        __syncthreads();
    }
    if (tid < NP) {
#pragma unroll
        for (int a = 0; a < NA; a++) {
            float2 f = upk(acc[a]);
            s_M[a * NP + tid] = f.x + f.y;
        }
    }
    __syncthreads();

    // ---- attn1: softmax over p of D = relu(M*ra*rp)*20 (warp per row) ----
    for (int r = wid; r < NA; r += 8) {
        const float ra = s_ra[r];
        float x[6];
        float mx = 0.f;   // all values >= 0 after relu
#pragma unroll
        for (int j = 0; j < 6; j++) {
            int p = lane + j * 32;
            float d = fmaxf(s_M[r * NP + p] * ra * s_rp[p], 0.f) * 20.f;
            x[j] = d; mx = fmaxf(mx, d);
        }
#pragma unroll
        for (int o = 16; o > 0; o >>= 1) mx = fmaxf(mx, __shfl_xor_sync(~0u, mx, o));
        float ssum = 0.f;
#pragma unroll
        for (int j = 0; j < 6; j++) { x[j] = __expf(x[j] - mx); ssum += x[j]; }
#pragma unroll
        for (int o = 16; o > 0; o >>= 1) ssum += __shfl_xor_sync(~0u, ssum, o);
        const float rinv = 1.f / ssum;
#pragma unroll
        for (int j = 0; j < 6; j++) s_A1[r * NP + lane + j * 32] = x[j] * rinv;
    }

    // ---- attn2 (masked softmax over a) + Gram quadratic form -> w_p ----
    if (tid < NP) {
        const int p = tid;
        const float rp = s_rp[p];
        float vv[NA];
        float mx = 0.f;
#pragma unroll
        for (int a = 0; a < NA; a++) {
            float d = fmaxf(s_M[a * NP + p] * s_ra[a] * rp, 0.f) * 20.f;
            if (s_padf[a] == 0.f) { vv[a] = d; mx = fmaxf(mx, d); }
            else                  { vv[a] = -1.f; }   // sentinel (valid d >= 0)
        }
        float ssum = 0.f;
#pragma unroll
        for (int a = 0; a < NA; a++) {
            float e = (vv[a] < 0.f) ? 0.f : __expf(vv[a] - mx);
            vv[a] = e; ssum += e;
        }
        const float rinv = 1.f / ssum;
#pragma unroll
        for (int a = 0; a < NA; a++) { vv[a] *= rinv; s_A2[a * NP + p] = vv[a]; }
        // ||r_p||^2 = attn2_p^T G attn2_p
        float z = 0.f;
#pragma unroll 1
        for (int b = 0; b < NA; b++) {
            const float* Gr = s_G + b * 32;
            float yb = 0.f;
#pragma unroll
            for (int a = 0; a < NA; a++) yb = fmaf(vv[a], Gr[a], yb);
            z = fmaf(yb, vv[b], z);
        }
        s_w[p] = rsqrtf(fmaxf(z, 1e-24f));
    }
    __syncthreads();

    // ---- Stage C: ||attend_patch_a||^2 via direct e-accumulation ----
    {
        const int e4 = tid & 63, h = tid >> 6;
        if (h < 3) stage_c<8>(pbase, s_A1, s_red, e4, h);
        else       stage_c<6>(pbase, s_A1, s_red, e4, h);
    }
    __syncthreads();
    if (tid < NA) {
        const int hh = tid >> 3, al = tid & 7;
        float ss2 = s_red[(hh * 2) * 8 + al] + s_red[(hh * 2 + 1) * 8 + al];
        s_w2[tid] = (s_padf[tid] != 0.f) ? 0.f : rsqrtf(fmaxf(ss2, 1e-24f));
    }
    __syncthreads();

    // ---- c_a = sum_p attn2[a][p] * w_p  (warp per row) ----
    for (int r = wid; r < NA; r += 8) {
        float cc = 0.f;
#pragma unroll
        for (int j = 0; j < 6; j++) {
            int p = lane + j * 32;
            cc = fmaf(s_A2[r * NP + p], s_w[p], cc);
        }
#pragma unroll
        for (int o = 16; o > 0; o >>= 1) cc += __shfl_xor_sync(~0u, cc, o);
        if (lane == 0) s_c[r] = cc;
    }
    __syncthreads();

    // ---- final: sim = sum_p d_p * (sum_a c_a M[a][p]) / (an*30) ----
    float fp = 0.f;
    if (tid < NP) {
        const int p = tid;
        float dp = 0.f, mp = 0.f;
#pragma unroll
        for (int a = 0; a < NA; a++) {
            dp = fmaf(s_A1[a * NP + p], s_w2[a], dp);
            mp = fmaf(s_c[a], s_M[a * NP + p], mp);
        }
        fp = dp * mp;
    }
#pragma unroll
    for (int o = 16; o > 0; o >>= 1) fp += __shfl_xor_sync(~0u, fp, o);
    if (lane == 0) s_red[wid] = fp;
    __syncthreads();
    if (tid == 0) {
        float tot = 0.f;
#pragma unroll
        for (int w2 = 0; w2 < 8; w2++) tot += s_red[w2];
        out_sim[t * NB + v] = tot / (s_an[0] * (float)NA);
    }
}

// ---------------------------------------------------------------------------
extern "C" void kernel_launch(void* const* d_in, const int* in_sizes, int n_in,
                              void* d_out, int out_size)
{
    const float* vf      = (const float*)d_in[0];
    const float* tf      = (const float*)d_in[1];
    const int*   mask    = (const int*)d_in[2];
    const int*   att_num = (const int*)d_in[3];
    const float* W_vis   = (const float*)d_in[4];
    const float* b_vis   = (const float*)d_in[5];
    const float* W_txt   = (const float*)d_in[6];
    const float* b_txt   = (const float*)d_in[7];
    const float* W_patch = (const float*)d_in[8];
    const float* b_patch = (const float*)d_in[9];
    const float* W_att   = (const float*)d_in[10];
    const float* b_att   = (const float*)d_in[11];
    float* out = (float*)d_out;

    void* p_patch = nullptr;
    void* p_att = nullptr;
    cudaGetSymbolAddress(&p_patch, g_patch);
    cudaGetSymbolAddress(&p_att, g_att);

    dim3 blk(256);
    proj_kernel<<<dim3(4, (NB * NP + 63) / 64), blk>>>(vf, W_patch, b_patch,
                                                       (float*)p_patch, NB * NP, SV, NP, 1);
    proj_kernel<<<dim3(4, (NB * NA + 63) / 64), blk>>>(tf, W_att, b_att,
                                                       (float*)p_att, NB * NA, ST, NA, 1);
    cls_kernel<<<2048, blk>>>(vf, tf, W_vis, b_vis, W_txt, b_txt, out);

    {
        int nrows = NB * NP + NB * NA;
        norm_kernel<<<(nrows + 7) / 8, blk>>>();
    }
    gram_kernel<<<NB, blk>>>();
    mean_kernel<<<NB, blk>>>(att_num, out);

    const int smem_bytes = SMEM_F * 4;
    cudaFuncSetAttribute(pair_kernel, cudaFuncAttributeMaxDynamicSharedMemorySize,
                         smem_bytes);
    pair_kernel<<<dim3(NB, NB), blk, smem_bytes>>>(mask, att_num, out + SIM_OFF);
}

// round 3
// speedup vs baseline: 1.4392x; 1.0063x over previous
#include <cuda_runtime.h>
#include <math.h>

// Problem constants
#define NB 32     // batch
#define NP 192    // patches
#define NA 30     // attributes
#define NE 256    // embed dim
#define NK 768    // input feature dim
#define SV 193    // visual seq len
#define ST 31     // textual seq len

#define VE_OFF 0
#define TE_OFF 8192
#define PM_OFF 16384
#define AM_OFF 24576
#define SIM_OFF 32768

// Scratch
__device__ float g_patch[NB * NP * NE];    // [v][p][e]
__device__ float g_patchT[NB * NE * NP];   // [v][e][p]
__device__ float g_att[NB * NA * NE];
__device__ float g_rp[NB * NP];
__device__ float g_ra[NB * NA];
__device__ float g_G[NB * NA * 32];

typedef unsigned long long ull;

__device__ __forceinline__ void fma2(ull& d, ull a, ull b) {
    asm("fma.rn.f32x2 %0, %1, %2, %3;" : "=l"(d) : "l"(a), "l"(b), "l"(d));
}
__device__ __forceinline__ ull pk2(float x, float y) {
    ull r; asm("mov.b64 %0, {%1,%2};" : "=l"(r) : "f"(x), "f"(y)); return r;
}
__device__ __forceinline__ float2 upk(ull v) {
    float2 r; asm("mov.b64 {%0,%1}, %2;" : "=f"(r.x), "=f"(r.y) : "l"(v)); return r;
}

// ---------------------------------------------------------------------------
// Projection GEMM with f32x2 microtile: out[m][n] = X[row(m)].W[n] + bias[n]
// ---------------------------------------------------------------------------
__global__ __launch_bounds__(256) void proj_kernel(
    const float* __restrict__ X, const float* __restrict__ W,
    const float* __restrict__ bias, float* __restrict__ out,
    int M, int S, int gs, int off)
{
    __shared__ float As[64][20];
    __shared__ float Bs[16][68];

    const int tid = threadIdx.x;
    const int col0 = blockIdx.x * 64;
    const int row0 = blockIdx.y * 64;
    const int tm = tid >> 4;
    const int tn = tid & 15;

    ull c2[4][2];
#pragma unroll
    for (int i = 0; i < 4; i++) { c2[i][0] = 0ull; c2[i][1] = 0ull; }

    const int lm = tid >> 2;
    const int lk = (tid & 3) << 2;
    const int grow = row0 + lm;
    const bool rowok = (grow < M);
    size_t srcrow = 0;
    if (rowok) srcrow = (size_t)((grow / gs) * S + off + grow % gs) * NK;
    const size_t wrow = (size_t)(col0 + lm) * NK;

    for (int k0 = 0; k0 < NK; k0 += 16) {
        float4 av = make_float4(0.f, 0.f, 0.f, 0.f);
        if (rowok) av = *(const float4*)&X[srcrow + k0 + lk];
        *(float4*)&As[lm][lk] = av;
        float4 bv = *(const float4*)&W[wrow + k0 + lk];
        Bs[lk + 0][lm] = bv.x;
        Bs[lk + 1][lm] = bv.y;
        Bs[lk + 2][lm] = bv.z;
        Bs[lk + 3][lm] = bv.w;
        __syncthreads();

#pragma unroll
        for (int k = 0; k < 16; k++) {
            ulonglong2 bb = *(ulonglong2*)&Bs[k][tn * 4];
            float a0 = As[tm * 4 + 0][k];
            float a1 = As[tm * 4 + 1][k];
            float a2 = As[tm * 4 + 2][k];
            float a3 = As[tm * 4 + 3][k];
            ull d0 = pk2(a0, a0), d1 = pk2(a1, a1);
            ull d2 = pk2(a2, a2), d3 = pk2(a3, a3);
            fma2(c2[0][0], d0, bb.x); fma2(c2[0][1], d0, bb.y);
            fma2(c2[1][0], d1, bb.x); fma2(c2[1][1], d1, bb.y);
            fma2(c2[2][0], d2, bb.x); fma2(c2[2][1], d2, bb.y);
            fma2(c2[3][0], d3, bb.x); fma2(c2[3][1], d3, bb.y);
        }
        __syncthreads();
    }

    const float4 b4 = *(const float4*)&bias[col0 + tn * 4];
#pragma unroll
    for (int i = 0; i < 4; i++) {
        int r = row0 + tm * 4 + i;
        if (r < M) {
            float2 lo = upk(c2[i][0]), hi = upk(c2[i][1]);
            float4 o;
            o.x = lo.x + b4.x; o.y = lo.y + b4.y;
            o.z = hi.x + b4.z; o.w = hi.y + b4.w;
            *(float4*)&out[(size_t)r * NE + col0 + tn * 4] = o;
        }
    }
}

// ---------------------------------------------------------------------------
// Transpose g_patch [v][p][e] -> g_patchT [v][e][p]. 32x32 smem tiles.
// grid (6, 8, 32): p-tile, e-tile, v. block 256 = 32x8.
// ---------------------------------------------------------------------------
__global__ __launch_bounds__(256) void transpose_kernel()
{
    __shared__ float ts[32][33];
    const int tx = threadIdx.x & 31, ty = threadIdx.x >> 5;
    const int p0 = blockIdx.x * 32, e0 = blockIdx.y * 32, v = blockIdx.z;
    const float* src = g_patch + (size_t)v * NP * NE;
    float* dst = g_patchT + (size_t)v * NE * NP;
#pragma unroll
    for (int k = 0; k < 4; k++)
        ts[ty + 8 * k][tx] = src[(size_t)(p0 + ty + 8 * k) * NE + e0 + tx];
    __syncthreads();
#pragma unroll
    for (int k = 0; k < 4; k++)
        dst[(size_t)(e0 + ty + 8 * k) * NP + p0 + tx] = ts[tx][ty + 8 * k];
}

// ---------------------------------------------------------------------------
// cls projections, warp per output dot
// ---------------------------------------------------------------------------
__global__ __launch_bounds__(256) void cls_kernel(
    const float* __restrict__ vf, const float* __restrict__ tf,
    const float* __restrict__ Wv, const float* __restrict__ bv,
    const float* __restrict__ Wt, const float* __restrict__ bt,
    float* __restrict__ out)
{
    const int wg = (blockIdx.x * 256 + threadIdx.x) >> 5;
    const int lane = threadIdx.x & 31;
    const int half = wg >> 13;
    const int o = wg & 8191;
    const int b = o >> 8, n = o & 255;
    const float* X = half ? (tf + (size_t)b * ST * NK) : (vf + (size_t)b * SV * NK);
    const float* W = (half ? Wt : Wv) + (size_t)n * NK;
    float acc = 0.f;
#pragma unroll
    for (int j = 0; j < 6; j++) {
        float4 x = *(const float4*)&X[lane * 4 + j * 128];
        float4 w = *(const float4*)&W[lane * 4 + j * 128];
        acc += x.x * w.x + x.y * w.y + x.z * w.z + x.w * w.w;
    }
#pragma unroll
    for (int off = 16; off > 0; off >>= 1) acc += __shfl_xor_sync(~0u, acc, off);
    if (lane == 0)
        out[(half ? TE_OFF : VE_OFF) + b * NE + n] = acc + (half ? bt : bv)[n];
}

// ---------------------------------------------------------------------------
__global__ __launch_bounds__(256) void norm_kernel()
{
    const int w = (blockIdx.x * blockDim.x + threadIdx.x) >> 5;
    const int lane = threadIdx.x & 31;
    if (w >= NB * NP + NB * NA) return;
    const float* row;
    float* dst;
    if (w < NB * NP) { row = g_patch + (size_t)w * NE; dst = &g_rp[w]; }
    else            { row = g_att + (size_t)(w - NB * NP) * NE; dst = &g_ra[w - NB * NP]; }
    float4 x0 = *(const float4*)&row[lane * 4];
    float4 x1 = *(const float4*)&row[128 + lane * 4];
    float ss = x0.x * x0.x + x0.y * x0.y + x0.z * x0.z + x0.w * x0.w
             + x1.x * x1.x + x1.y * x1.y + x1.z * x1.z + x1.w * x1.w;
#pragma unroll
    for (int o = 16; o > 0; o >>= 1) ss += __shfl_xor_sync(~0u, ss, o);
    if (lane == 0) *dst = rsqrtf(fmaxf(ss, 1e-24f));
}

// ---------------------------------------------------------------------------
__global__ __launch_bounds__(256) void gram_kernel()
{
    __shared__ float s[NA * NE];
    const int t = blockIdx.x, tid = threadIdx.x;
    const float* ap = g_att + (size_t)t * NA * NE;
    for (int i = tid; i < NA * NE; i += 256) s[i] = ap[i];
    __syncthreads();
    for (int idx = tid; idx < NA * NA; idx += 256) {
        int a = idx / NA, b = idx % NA;
        const float* ra = s + a * NE;
        const float* rb = s + b * NE;
        float acc = 0.f;
#pragma unroll 4
        for (int e = 0; e < NE; e += 4) {
            float4 x = *(float4*)&ra[e];
            float4 y = *(float4*)&rb[e];
            acc += x.x * y.x + x.y * y.y + x.z * y.z + x.w * y.w;
        }
        g_G[t * NA * 32 + a * 32 + b] = acc;
    }
}

// ---------------------------------------------------------------------------
__global__ __launch_bounds__(256) void mean_kernel(const int* __restrict__ att_nums,
                                                   float* __restrict__ out)
{
    const int b = blockIdx.x;
    const int e = threadIdx.x;
    float pm = 0.f;
    const float* pb = g_patch + (size_t)b * NP * NE + e;
#pragma unroll 4
    for (int p = 0; p < NP; p++) pm += pb[(size_t)p * NE];
    out[PM_OFF + b * NE + e] = pm / (float)NP;

    float am = 0.f;
    const float* ab = g_att + (size_t)b * NA * NE + e;
#pragma unroll
    for (int a = 0; a < NA; a++) am += ab[(size_t)a * NE];
    out[AM_OFF + b * NE + e] = am / (float)att_nums[b];
}

// ---------------------------------------------------------------------------
// Pair kernel smem layout (floats)
// ---------------------------------------------------------------------------
#define SA_ATT  0          /* 8192 : att padded to 32 rows, zeros beyond 30 */
#define SA_M    8192       /* 6144 : M [32][192] */
#define SA_A1   14336      /* 5760 */
#define SA_TILE 20096      /* 2 * 32 * 196 = 12544 */
#define SA_G    32640      /* 960 */
#define SA_RA   33600      /* 32 */
#define SA_RP   33632      /* 192 */
#define SA_PADF 33824      /* 32 */
#define SA_W    33856      /* 192 */
#define SA_W2   34048      /* 32 */
#define SA_C    34080      /* 32 */
#define SA_RED  34112      /* 64 */
#define SA_AN   34176      /* 1 */
#define SMEM_F  34180
#define TILE_LD 196

// Stage C helper: ||attend_patch_a||^2 partials (f32x2 over e, 8 a's / group)
template<int NAq>
__device__ __forceinline__ void stage_c(const float* __restrict__ pbase,
                                        const float* __restrict__ s_A1,
                                        float* __restrict__ s_red,
                                        int e4, int h)
{
    ull acc[NAq][2];
#pragma unroll
    for (int a = 0; a < NAq; a++) { acc[a][0] = 0ull; acc[a][1] = 0ull; }
    const int a0 = h * 8;
#pragma unroll 1
    for (int p0 = 0; p0 < NP; p0 += 4) {
        ulonglong2 u0 = *(const ulonglong2*)&pbase[(size_t)(p0 + 0) * NE + e4 * 4];
        ulonglong2 u1 = *(const ulonglong2*)&pbase[(size_t)(p0 + 1) * NE + e4 * 4];
        ulonglong2 u2 = *(const ulonglong2*)&pbase[(size_t)(p0 + 2) * NE + e4 * 4];
        ulonglong2 u3 = *(const ulonglong2*)&pbase[(size_t)(p0 + 3) * NE + e4 * 4];
#pragma unroll
        for (int a = 0; a < NAq; a++) {
            float4 q = *(const float4*)&s_A1[(a0 + a) * NP + p0];
            ull w0 = pk2(q.x, q.x), w1 = pk2(q.y, q.y);
            ull w2 = pk2(q.z, q.z), w3 = pk2(q.w, q.w);
            fma2(acc[a][0], w0, u0.x); fma2(acc[a][1], w0, u0.y);
            fma2(acc[a][0], w1, u1.x); fma2(acc[a][1], w1, u1.y);
            fma2(acc[a][0], w2, u2.x); fma2(acc[a][1], w2, u2.y);
            fma2(acc[a][0], w3, u3.x); fma2(acc[a][1], w3, u3.y);
        }
    }
    const int lane = threadIdx.x & 31, warp = threadIdx.x >> 5;
#pragma unroll
    for (int a = 0; a < NAq; a++) {
        float2 f0 = upk(acc[a][0]), f1 = upk(acc[a][1]);
        float s = f0.x * f0.x + f0.y * f0.y + f1.x * f1.x + f1.y * f1.y;
#pragma unroll
        for (int o = 16; o > 0; o >>= 1) s += __shfl_xor_sync(~0u, s, o);
        if (lane == 0) s_red[warp * 8 + a] = s;
    }
}

// ---------------------------------------------------------------------------
// Fused per-(t,v) pair kernel. 256 threads, ~137 KB smem (1 block/SM).
// ---------------------------------------------------------------------------
__global__ __launch_bounds__(256) void pair_kernel(const int* __restrict__ mask,
                                                   const int* __restrict__ att_nums,
                                                   float* __restrict__ out_sim)
{
    extern __shared__ float sm[];
    const int v = blockIdx.x, t = blockIdx.y;
    const int tid = threadIdx.x, lane = tid & 31, wid = tid >> 5;

    float* s_att  = sm + SA_ATT;
    float* s_M    = sm + SA_M;
    float* s_A1   = sm + SA_A1;
    float* s_A2   = sm + SA_ATT;    // alias: att dead after stage A
    float* s_tile = sm + SA_TILE;
    float* s_G    = sm + SA_G;
    float* s_ra   = sm + SA_RA;
    float* s_rp   = sm + SA_RP;
    float* s_padf = sm + SA_PADF;
    float* s_w    = sm + SA_W;
    float* s_w2   = sm + SA_W2;
    float* s_c    = sm + SA_C;
    float* s_red  = sm + SA_RED;
    float* s_an   = sm + SA_AN;

    // ---- preload (att padded to 32 rows with zeros) ----
    const float* attp = g_att + (size_t)t * NA * NE;
    for (int i = tid; i < 32 * NE; i += 256)
        s_att[i] = (i < NA * NE) ? attp[i] : 0.f;
    const float* gGp = g_G + t * NA * 32;
    for (int i = tid; i < NA * 32; i += 256) s_G[i] = gGp[i];
    if (tid < NA) {
        s_ra[tid] = g_ra[t * NA + tid];
        s_padf[tid] = (mask[t * NA + tid] != 0) ? 1.f : 0.f;
    }
    if (tid < NP) s_rp[tid] = g_rp[v * NP + tid];
    if (tid == 0) s_an[0] = (float)att_nums[t];
    __syncthreads();

    const float* pbase = g_patch + (size_t)v * NP * NE;
    const float* ptv   = g_patchT + (size_t)v * NE * NP;

    // ---- Stage A: M[a][p] = att_a . patch_p. 8a x 6p microtile, e-split 2 ----
    {
        const int eg = tid >> 7;          // e-half
        const int g  = tid & 127;
        const int at = g >> 5;            // warp-within-group = a-tile
        const int pt = g & 31;
        const int a0 = at * 8, p0 = pt * 6;
        float* my_tile = s_tile + eg * (32 * TILE_LD);

        ull acc[8][3];
#pragma unroll
        for (int a = 0; a < 8; a++) { acc[a][0] = acc[a][1] = acc[a][2] = 0ull; }

        for (int c = 0; c < 4; c++) {
            const int e0 = eg * 128 + c * 32;
            // group loads its own 32x192 transposed tile (coalesced float4)
#pragma unroll
            for (int i = 0; i < 12; i++) {
                int fid = g + 128 * i;          // 0..1535
                int row = fid / 48, col = (fid % 48) * 4;
                *(float4*)&my_tile[row * TILE_LD + col] =
                    *(const float4*)&ptv[(size_t)(e0 + row) * NP + col];
            }
            __syncthreads();
#pragma unroll
            for (int e4 = 0; e4 < 32; e4 += 4) {
                float4 av[8];
#pragma unroll
                for (int a = 0; a < 8; a++)
                    av[a] = *(const float4*)&s_att[(a0 + a) * NE + e0 + e4];
#pragma unroll
                for (int j = 0; j < 4; j++) {
                    const float* tr = &my_tile[(e4 + j) * TILE_LD + p0];
                    ull p01 = *(const ull*)&tr[0];
                    ull p23 = *(const ull*)&tr[2];
                    ull p45 = *(const ull*)&tr[4];
#pragma unroll
                    for (int a = 0; a < 8; a++) {
                        float aval = (j == 0) ? av[a].x : (j == 1) ? av[a].y
                                   : (j == 2) ? av[a].z : av[a].w;
                        ull ad = pk2(aval, aval);
                        fma2(acc[a][0], ad, p01);
                        fma2(acc[a][1], ad, p23);
                        fma2(acc[a][2], ad, p45);
                    }
                }
            }
            __syncthreads();
        }
        // combine the two e-halves into s_M
        if (eg == 1) {
#pragma unroll
            for (int a = 0; a < 8; a++)
#pragma unroll
                for (int jj = 0; jj < 3; jj++) {
                    float2 f = upk(acc[a][jj]);
                    *(float2*)&s_M[(a0 + a) * NP + p0 + 2 * jj] = f;
                }
        }
        __syncthreads();
        if (eg == 0) {
#pragma unroll
            for (int a = 0; a < 8; a++)
#pragma unroll
                for (int jj = 0; jj < 3; jj++) {
                    float2 f = upk(acc[a][jj]);
                    float2 o = *(float2*)&s_M[(a0 + a) * NP + p0 + 2 * jj];
                    o.x += f.x; o.y += f.y;
                    *(float2*)&s_M[(a0 + a) * NP + p0 + 2 * jj] = o;
                }
        }
        __syncthreads();
    }

    // ---- attn1: softmax over p of D = relu(M*ra*rp)*20 (warp per row) ----
    for (int r = wid; r < NA; r += 8) {
        const float ra = s_ra[r];
        float x[6];
        float mx = 0.f;
#pragma unroll
        for (int j = 0; j < 6; j++) {
            int p = lane + j * 32;
            float d = fmaxf(s_M[r * NP + p] * ra * s_rp[p], 0.f) * 20.f;
            x[j] = d; mx = fmaxf(mx, d);
        }
#pragma unroll
        for (int o = 16; o > 0; o >>= 1) mx = fmaxf(mx, __shfl_xor_sync(~0u, mx, o));
        float ssum = 0.f;
#pragma unroll
        for (int j = 0; j < 6; j++) { x[j] = __expf(x[j] - mx); ssum += x[j]; }
#pragma unroll
        for (int o = 16; o > 0; o >>= 1) ssum += __shfl_xor_sync(~0u, ssum, o);
        const float rinv = 1.f / ssum;
#pragma unroll
        for (int j = 0; j < 6; j++) s_A1[r * NP + lane + j * 32] = x[j] * rinv;
    }

    // ---- attn2 (masked softmax over a) + Gram quadratic -> w_p ----
    if (tid < NP) {
        const int p = tid;
        const float rp = s_rp[p];
        float vv[NA];
        float mx = 0.f;
#pragma unroll
        for (int a = 0; a < NA; a++) {
            float d = fmaxf(s_M[a * NP + p] * s_ra[a] * rp, 0.f) * 20.f;
            if (s_padf[a] == 0.f) { vv[a] = d; mx = fmaxf(mx, d); }
            else                  { vv[a] = -1.f; }
        }
        float ssum = 0.f;
#pragma unroll
        for (int a = 0; a < NA; a++) {
            float e = (vv[a] < 0.f) ? 0.f : __expf(vv[a] - mx);
            vv[a] = e; ssum += e;
        }
        const float rinv = 1.f / ssum;
#pragma unroll
        for (int a = 0; a < NA; a++) { vv[a] *= rinv; s_A2[a * NP + p] = vv[a]; }
        float z = 0.f;
#pragma unroll 1
        for (int b = 0; b < NA; b++) {
            const float* Gr = s_G + b * 32;
            float yb = 0.f;
#pragma unroll
            for (int a = 0; a < NA; a++) yb = fmaf(vv[a], Gr[a], yb);
            z = fmaf(yb, vv[b], z);
        }
        s_w[p] = rsqrtf(fmaxf(z, 1e-24f));
    }
    __syncthreads();

    // ---- Stage C: ||attend_patch_a||^2 ----
    {
        const int e4 = tid & 63, h = tid >> 6;
        if (h < 3) stage_c<8>(pbase, s_A1, s_red, e4, h);
        else       stage_c<6>(pbase, s_A1, s_red, e4, h);
    }
    __syncthreads();
    if (tid < NA) {
        const int hh = tid >> 3, al = tid & 7;
        float ss2 = s_red[(hh * 2) * 8 + al] + s_red[(hh * 2 + 1) * 8 + al];
        s_w2[tid] = (s_padf[tid] != 0.f) ? 0.f : rsqrtf(fmaxf(ss2, 1e-24f));
    }
    __syncthreads();

    // ---- c_a = sum_p attn2[a][p] * w_p ----
    for (int r = wid; r < NA; r += 8) {
        float cc = 0.f;
#pragma unroll
        for (int j = 0; j < 6; j++) {
            int p = lane + j * 32;
            cc = fmaf(s_A2[r * NP + p], s_w[p], cc);
        }
#pragma unroll
        for (int o = 16; o > 0; o >>= 1) cc += __shfl_xor_sync(~0u, cc, o);
        if (lane == 0) s_c[r] = cc;
    }
    __syncthreads();

    // ---- final: sim = sum_p d_p * (sum_a c_a M[a][p]) / (an*30) ----
    float fp = 0.f;
    if (tid < NP) {
        const int p = tid;
        float dp = 0.f, mp = 0.f;
#pragma unroll
        for (int a = 0; a < NA; a++) {
            dp = fmaf(s_A1[a * NP + p], s_w2[a], dp);
            mp = fmaf(s_c[a], s_M[a * NP + p], mp);
        }
        fp = dp * mp;
    }
#pragma unroll
    for (int o = 16; o > 0; o >>= 1) fp += __shfl_xor_sync(~0u, fp, o);
    if (lane == 0) s_red[wid] = fp;
    __syncthreads();
    if (tid == 0) {
        float tot = 0.f;
#pragma unroll
        for (int w2 = 0; w2 < 8; w2++) tot += s_red[w2];
        out_sim[t * NB + v] = tot / (s_an[0] * (float)NA);
    }
}

// ---------------------------------------------------------------------------
extern "C" void kernel_launch(void* const* d_in, const int* in_sizes, int n_in,
                              void* d_out, int out_size)
{
    const float* vf      = (const float*)d_in[0];
    const float* tf      = (const float*)d_in[1];
    const int*   mask    = (const int*)d_in[2];
    const int*   att_num = (const int*)d_in[3];
    const float* W_vis   = (const float*)d_in[4];
    const float* b_vis   = (const float*)d_in[5];
    const float* W_txt   = (const float*)d_in[6];
    const float* b_txt   = (const float*)d_in[7];
    const float* W_patch = (const float*)d_in[8];
    const float* b_patch = (const float*)d_in[9];
    const float* W_att   = (const float*)d_in[10];
    const float* b_att   = (const float*)d_in[11];
    float* out = (float*)d_out;

    void* p_patch = nullptr;
    void* p_att = nullptr;
    cudaGetSymbolAddress(&p_patch, g_patch);
    cudaGetSymbolAddress(&p_att, g_att);

    dim3 blk(256);
    proj_kernel<<<dim3(4, (NB * NP + 63) / 64), blk>>>(vf, W_patch, b_patch,
                                                       (float*)p_patch, NB * NP, SV, NP, 1);
    proj_kernel<<<dim3(4, (NB * NA + 63) / 64), blk>>>(tf, W_att, b_att,
                                                       (float*)p_att, NB * NA, ST, NA, 1);
    cls_kernel<<<2048, blk>>>(vf, tf, W_vis, b_vis, W_txt, b_txt, out);

    transpose_kernel<<<dim3(6, 8, 32), blk>>>();

    {
        int nrows = NB * NP + NB * NA;
        norm_kernel<<<(nrows + 7) / 8, blk>>>();
    }
    gram_kernel<<<NB, blk>>>();
    mean_kernel<<<NB, blk>>>(att_num, out);

    const int smem_bytes = SMEM_F * 4;
    cudaFuncSetAttribute(pair_kernel, cudaFuncAttributeMaxDynamicSharedMemorySize,
                         smem_bytes);
    pair_kernel<<<dim3(NB, NB), blk, smem_bytes>>>(mask, att_num, out + SIM_OFF);
}

// round 4
// speedup vs baseline: 1.5766x; 1.0955x over previous
#include <cuda_runtime.h>
#include <math.h>

// Problem constants
#define NB 32     // batch
#define NP 192    // patches
#define NA 30     // attributes
#define NE 256    // embed dim
#define NK 768    // input feature dim
#define SV 193    // visual seq len
#define ST 31     // textual seq len

#define VE_OFF 0
#define TE_OFF 8192
#define PM_OFF 16384
#define AM_OFF 24576
#define SIM_OFF 32768

// Scratch
__device__ float g_patch[NB * NP * NE];    // [v][p][e]
__device__ float g_patchT[NB * NE * NP];   // [v][e][p]
__device__ float g_att[NB * NA * NE];
__device__ float g_rp[NB * NP];
__device__ float g_ra[NB * NA];
__device__ float g_G[NB * NA * 32];

typedef unsigned long long ull;

__device__ __forceinline__ void fma2(ull& d, ull a, ull b) {
    asm("fma.rn.f32x2 %0, %1, %2, %3;" : "=l"(d) : "l"(a), "l"(b), "l"(d));
}
__device__ __forceinline__ ull pk2(float x, float y) {
    ull r; asm("mov.b64 %0, {%1,%2};" : "=l"(r) : "f"(x), "f"(y)); return r;
}
__device__ __forceinline__ float2 upk(ull v) {
    float2 r; asm("mov.b64 {%0,%1}, %2;" : "=f"(r.x), "=f"(r.y) : "l"(v)); return r;
}

// ---------------------------------------------------------------------------
// Projection GEMM with f32x2 microtile: out[m][n] = X[row(m)].W[n] + bias[n]
// ---------------------------------------------------------------------------
__global__ __launch_bounds__(256) void proj_kernel(
    const float* __restrict__ X, const float* __restrict__ W,
    const float* __restrict__ bias, float* __restrict__ out,
    int M, int S, int gs, int off)
{
    __shared__ float As[64][20];
    __shared__ float Bs[16][68];

    const int tid = threadIdx.x;
    const int col0 = blockIdx.x * 64;
    const int row0 = blockIdx.y * 64;
    const int tm = tid >> 4;
    const int tn = tid & 15;

    ull c2[4][2];
#pragma unroll
    for (int i = 0; i < 4; i++) { c2[i][0] = 0ull; c2[i][1] = 0ull; }

    const int lm = tid >> 2;
    const int lk = (tid & 3) << 2;
    const int grow = row0 + lm;
    const bool rowok = (grow < M);
    size_t srcrow = 0;
    if (rowok) srcrow = (size_t)((grow / gs) * S + off + grow % gs) * NK;
    const size_t wrow = (size_t)(col0 + lm) * NK;

    for (int k0 = 0; k0 < NK; k0 += 16) {
        float4 av = make_float4(0.f, 0.f, 0.f, 0.f);
        if (rowok) av = *(const float4*)&X[srcrow + k0 + lk];
        *(float4*)&As[lm][lk] = av;
        float4 bv = *(const float4*)&W[wrow + k0 + lk];
        Bs[lk + 0][lm] = bv.x;
        Bs[lk + 1][lm] = bv.y;
        Bs[lk + 2][lm] = bv.z;
        Bs[lk + 3][lm] = bv.w;
        __syncthreads();

#pragma unroll
        for (int k = 0; k < 16; k++) {
            ulonglong2 bb = *(ulonglong2*)&Bs[k][tn * 4];
            float a0 = As[tm * 4 + 0][k];
            float a1 = As[tm * 4 + 1][k];
            float a2 = As[tm * 4 + 2][k];
            float a3 = As[tm * 4 + 3][k];
            ull d0 = pk2(a0, a0), d1 = pk2(a1, a1);
            ull d2 = pk2(a2, a2), d3 = pk2(a3, a3);
            fma2(c2[0][0], d0, bb.x); fma2(c2[0][1], d0, bb.y);
            fma2(c2[1][0], d1, bb.x); fma2(c2[1][1], d1, bb.y);
            fma2(c2[2][0], d2, bb.x); fma2(c2[2][1], d2, bb.y);
            fma2(c2[3][0], d3, bb.x); fma2(c2[3][1], d3, bb.y);
        }
        __syncthreads();
    }

    const float4 b4 = *(const float4*)&bias[col0 + tn * 4];
#pragma unroll
    for (int i = 0; i < 4; i++) {
        int r = row0 + tm * 4 + i;
        if (r < M) {
            float2 lo = upk(c2[i][0]), hi = upk(c2[i][1]);
            float4 o;
            o.x = lo.x + b4.x; o.y = lo.y + b4.y;
            o.z = hi.x + b4.z; o.w = hi.y + b4.w;
            *(float4*)&out[(size_t)r * NE + col0 + tn * 4] = o;
        }
    }
}

// ---------------------------------------------------------------------------
// Fused prep kernel: transpose | norms | gram | means | cls projections
// grid x ranges: [0,1536) transpose, [1536,2424) norm, [2424,2456) gram,
//                [2456,2488) mean, [2488,4536) cls
// ---------------------------------------------------------------------------
__global__ __launch_bounds__(256) void prep_kernel(
    const float* __restrict__ vf, const float* __restrict__ tf,
    const float* __restrict__ Wv, const float* __restrict__ bv,
    const float* __restrict__ Wt, const float* __restrict__ bt,
    const int* __restrict__ att_nums, float* __restrict__ out)
{
    __shared__ float sbuf[NA * NE];   // gram uses all; transpose uses 32x33
    const int r = blockIdx.x;
    const int tid = threadIdx.x;
    const int lane = tid & 31, wid = tid >> 5;

    if (r < 1536) {
        // -------- transpose g_patch [v][p][e] -> g_patchT [v][e][p] --------
        float (*ts)[33] = (float (*)[33])sbuf;
        const int v = r / 48, rem = r % 48;
        const int e0 = (rem / 6) * 32, p0 = (rem % 6) * 32;
        const float* src = g_patch + (size_t)v * NP * NE;
        float* dst = g_patchT + (size_t)v * NE * NP;
#pragma unroll
        for (int k = 0; k < 4; k++)
            ts[wid + 8 * k][lane] = src[(size_t)(p0 + wid + 8 * k) * NE + e0 + lane];
        __syncthreads();
#pragma unroll
        for (int k = 0; k < 4; k++)
            dst[(size_t)(e0 + wid + 8 * k) * NP + p0 + lane] = ts[lane][wid + 8 * k];
    } else if (r < 2424) {
        // -------- inverse L2 norms (warp per row) --------
        const int w = (r - 1536) * 8 + wid;
        if (w >= NB * NP + NB * NA) return;
        const float* row;
        float* dst;
        if (w < NB * NP) { row = g_patch + (size_t)w * NE; dst = &g_rp[w]; }
        else { row = g_att + (size_t)(w - NB * NP) * NE; dst = &g_ra[w - NB * NP]; }
        float4 x0 = *(const float4*)&row[lane * 4];
        float4 x1 = *(const float4*)&row[128 + lane * 4];
        float ss = x0.x * x0.x + x0.y * x0.y + x0.z * x0.z + x0.w * x0.w
                 + x1.x * x1.x + x1.y * x1.y + x1.z * x1.z + x1.w * x1.w;
#pragma unroll
        for (int o = 16; o > 0; o >>= 1) ss += __shfl_xor_sync(~0u, ss, o);
        if (lane == 0) *dst = rsqrtf(fmaxf(ss, 1e-24f));
    } else if (r < 2456) {
        // -------- gram: G[t][a][b] = att_a . att_b --------
        const int t = r - 2424;
        const float* ap = g_att + (size_t)t * NA * NE;
        for (int i = tid; i < NA * NE; i += 256) sbuf[i] = ap[i];
        __syncthreads();
        for (int idx = tid; idx < NA * NA; idx += 256) {
            int a = idx / NA, b = idx % NA;
            const float* ra = sbuf + a * NE;
            const float* rb = sbuf + b * NE;
            float acc = 0.f;
#pragma unroll 4
            for (int e = 0; e < NE; e += 4) {
                float4 x = *(float4*)&ra[e];
                float4 y = *(float4*)&rb[e];
                acc += x.x * y.x + x.y * y.y + x.z * y.z + x.w * y.w;
            }
            g_G[t * NA * 32 + a * 32 + b] = acc;
        }
    } else if (r < 2488) {
        // -------- means --------
        const int b = r - 2456;
        const int e = tid;
        float pm = 0.f;
        const float* pb = g_patch + (size_t)b * NP * NE + e;
#pragma unroll 4
        for (int p = 0; p < NP; p++) pm += pb[(size_t)p * NE];
        out[PM_OFF + b * NE + e] = pm / (float)NP;
        float am = 0.f;
        const float* ab = g_att + (size_t)b * NA * NE + e;
#pragma unroll
        for (int a = 0; a < NA; a++) am += ab[(size_t)a * NE];
        out[AM_OFF + b * NE + e] = am / (float)att_nums[b];
    } else {
        // -------- cls projections (warp per output dot) --------
        const int wg = (r - 2488) * 8 + wid;
        const int half = wg >> 13;
        const int o = wg & 8191;
        const int b = o >> 8, n = o & 255;
        const float* X = half ? (tf + (size_t)b * ST * NK) : (vf + (size_t)b * SV * NK);
        const float* W = (half ? Wt : Wv) + (size_t)n * NK;
        float acc = 0.f;
#pragma unroll
        for (int j = 0; j < 6; j++) {
            float4 x = *(const float4*)&X[lane * 4 + j * 128];
            float4 w = *(const float4*)&W[lane * 4 + j * 128];
            acc += x.x * w.x + x.y * w.y + x.z * w.z + x.w * w.w;
        }
#pragma unroll
        for (int off = 16; off > 0; off >>= 1) acc += __shfl_xor_sync(~0u, acc, off);
        if (lane == 0)
            out[(half ? TE_OFF : VE_OFF) + b * NE + n] = acc + (half ? bt : bv)[n];
    }
}

// ---------------------------------------------------------------------------
// Pair kernel smem layout (floats). Total 28289 fl = 113156 B -> 2 CTAs/SM.
// ---------------------------------------------------------------------------
#define SA_ATT  0          /* 8192 : att padded to 32 rows (zeros) */
#define SA_M    8192       /* 6144 : M [32][192] */
#define SA_A1   14336      /* 6144 : attn1 padded to 32 rows (rows 30,31 zero) */
#define SA_TILE 20480      /* 6272 : stage A: 2x16x196; stage C: 16x256 */
#define SA_G    26752      /* 960 */
#define SA_RA   27712      /* 32 */
#define SA_RP   27744      /* 192 */
#define SA_PADF 27936      /* 32 */
#define SA_W    27968      /* 192 */
#define SA_W2   28160      /* 32 */
#define SA_C    28192      /* 32 */
#define SA_RED  28224      /* 64 */
#define SA_AN   28288      /* 1 */
#define SMEM_F  28289
#define TILE_LD 196

// Stage C per-tile compute: 16 p-rows from s_ctile [16][256], 8 a's.
__device__ __forceinline__ void stage_c_tile(const float* __restrict__ s_ctile,
                                             const float* __restrict__ s_A1,
                                             ull (&acc)[8][2], int e4, int a0, int p0)
{
#pragma unroll
    for (int pp = 0; pp < 16; pp += 4) {
        ulonglong2 u0 = *(const ulonglong2*)&s_ctile[(pp + 0) * NE + e4 * 4];
        ulonglong2 u1 = *(const ulonglong2*)&s_ctile[(pp + 1) * NE + e4 * 4];
        ulonglong2 u2 = *(const ulonglong2*)&s_ctile[(pp + 2) * NE + e4 * 4];
        ulonglong2 u3 = *(const ulonglong2*)&s_ctile[(pp + 3) * NE + e4 * 4];
#pragma unroll
        for (int a = 0; a < 8; a++) {
            float4 q = *(const float4*)&s_A1[(a0 + a) * NP + p0 + pp];
            ull w0 = pk2(q.x, q.x), w1 = pk2(q.y, q.y);
            ull w2 = pk2(q.z, q.z), w3 = pk2(q.w, q.w);
            fma2(acc[a][0], w0, u0.x); fma2(acc[a][1], w0, u0.y);
            fma2(acc[a][0], w1, u1.x); fma2(acc[a][1], w1, u1.y);
            fma2(acc[a][0], w2, u2.x); fma2(acc[a][1], w2, u2.y);
            fma2(acc[a][0], w3, u3.x); fma2(acc[a][1], w3, u3.y);
        }
    }
}

// ---------------------------------------------------------------------------
// Fused per-(t,v) pair kernel. 256 threads, 113 KB smem, 2 CTAs/SM.
// ---------------------------------------------------------------------------
__global__ __launch_bounds__(256, 2) void pair_kernel(const int* __restrict__ mask,
                                                      const int* __restrict__ att_nums,
                                                      float* __restrict__ out_sim)
{
    extern __shared__ float sm[];
    const int v = blockIdx.x, t = blockIdx.y;
    const int tid = threadIdx.x, lane = tid & 31, wid = tid >> 5;

    float* s_att  = sm + SA_ATT;
    float* s_M    = sm + SA_M;
    float* s_A1   = sm + SA_A1;
    float* s_A2   = sm + SA_ATT;    // alias: att dead after stage A
    float* s_tile = sm + SA_TILE;
    float* s_G    = sm + SA_G;
    float* s_ra   = sm + SA_RA;
    float* s_rp   = sm + SA_RP;
    float* s_padf = sm + SA_PADF;
    float* s_w    = sm + SA_W;
    float* s_w2   = sm + SA_W2;
    float* s_c    = sm + SA_C;
    float* s_red  = sm + SA_RED;
    float* s_an   = sm + SA_AN;

    // ---- preload ----
    const float* attp = g_att + (size_t)t * NA * NE;
    for (int i = tid; i < 32 * NE; i += 256)
        s_att[i] = (i < NA * NE) ? attp[i] : 0.f;
    const float* gGp = g_G + t * NA * 32;
    for (int i = tid; i < NA * 32; i += 256) s_G[i] = gGp[i];
    // zero attn1 pad rows 30,31 (stage C reads them as a uniform 32-row array)
    for (int i = tid; i < 2 * NP; i += 256) s_A1[NA * NP + i] = 0.f;
    if (tid < NA) {
        s_ra[tid] = g_ra[t * NA + tid];
        s_padf[tid] = (mask[t * NA + tid] != 0) ? 1.f : 0.f;
    }
    if (tid < NP) s_rp[tid] = g_rp[v * NP + tid];
    if (tid == 0) s_an[0] = (float)att_nums[t];
    __syncthreads();

    const float* pbase = g_patch + (size_t)v * NP * NE;
    const float* ptv   = g_patchT + (size_t)v * NE * NP;

    // ---- Stage A: M[a][p] = att_a . patch_p. 8a x 6p microtile, e-split 2 ----
    {
        const int eg = tid >> 7;          // e-half
        const int g  = tid & 127;
        const int at = g >> 5;            // warp-within-group = a-tile
        const int pt = g & 31;
        const int a0 = at * 8, p0 = pt * 6;
        float* my_tile = s_tile + eg * (16 * TILE_LD);

        ull acc[8][3];
#pragma unroll
        for (int a = 0; a < 8; a++) { acc[a][0] = acc[a][1] = acc[a][2] = 0ull; }

        for (int c = 0; c < 8; c++) {
            const int e0 = eg * 128 + c * 16;
            // group loads its 16x192 transposed tile (coalesced float4)
#pragma unroll
            for (int i = 0; i < 6; i++) {
                int fid = g + 128 * i;          // 0..767
                int row = fid / 48, col = (fid % 48) * 4;
                *(float4*)&my_tile[row * TILE_LD + col] =
                    *(const float4*)&ptv[(size_t)(e0 + row) * NP + col];
            }
            __syncthreads();
#pragma unroll
            for (int e4 = 0; e4 < 16; e4 += 4) {
                float4 av[8];
#pragma unroll
                for (int a = 0; a < 8; a++)
                    av[a] = *(const float4*)&s_att[(a0 + a) * NE + e0 + e4];
#pragma unroll
                for (int j = 0; j < 4; j++) {
                    const float* tr = &my_tile[(e4 + j) * TILE_LD + p0];
                    ull p01 = *(const ull*)&tr[0];
                    ull p23 = *(const ull*)&tr[2];
                    ull p45 = *(const ull*)&tr[4];
#pragma unroll
                    for (int a = 0; a < 8; a++) {
                        float aval = (j == 0) ? av[a].x : (j == 1) ? av[a].y
                                   : (j == 2) ? av[a].z : av[a].w;
                        ull ad = pk2(aval, aval);
                        fma2(acc[a][0], ad, p01);
                        fma2(acc[a][1], ad, p23);
                        fma2(acc[a][2], ad, p45);
                    }
                }
            }
            __syncthreads();
        }
        // combine the two e-halves into s_M
        if (eg == 1) {
#pragma unroll
            for (int a = 0; a < 8; a++)
#pragma unroll
                for (int jj = 0; jj < 3; jj++) {
                    float2 f = upk(acc[a][jj]);
                    *(float2*)&s_M[(a0 + a) * NP + p0 + 2 * jj] = f;
                }
        }
        __syncthreads();
        if (eg == 0) {
#pragma unroll
            for (int a = 0; a < 8; a++)
#pragma unroll
                for (int jj = 0; jj < 3; jj++) {
                    float2 f = upk(acc[a][jj]);
                    float2 o = *(float2*)&s_M[(a0 + a) * NP + p0 + 2 * jj];
                    o.x += f.x; o.y += f.y;
                    *(float2*)&s_M[(a0 + a) * NP + p0 + 2 * jj] = o;
                }
        }
        __syncthreads();
    }

    // ---- attn1: softmax over p of D = relu(M*ra*rp)*20 (warp per row) ----
    for (int r = wid; r < NA; r += 8) {
        const float ra = s_ra[r];
        float x[6];
        float mx = 0.f;
#pragma unroll
        for (int j = 0; j < 6; j++) {
            int p = lane + j * 32;
            float d = fmaxf(s_M[r * NP + p] * ra * s_rp[p], 0.f) * 20.f;
            x[j] = d; mx = fmaxf(mx, d);
        }
#pragma unroll
        for (int o = 16; o > 0; o >>= 1) mx = fmaxf(mx, __shfl_xor_sync(~0u, mx, o));
        float ssum = 0.f;
#pragma unroll
        for (int j = 0; j < 6; j++) { x[j] = __expf(x[j] - mx); ssum += x[j]; }
#pragma unroll
        for (int o = 16; o > 0; o >>= 1) ssum += __shfl_xor_sync(~0u, ssum, o);
        const float rinv = 1.f / ssum;
#pragma unroll
        for (int j = 0; j < 6; j++) s_A1[r * NP + lane + j * 32] = x[j] * rinv;
    }

    // ---- attn2 (masked softmax over a) + Gram quadratic -> w_p ----
    if (tid < NP) {
        const int p = tid;
        const float rp = s_rp[p];
        float vv[NA];
        float mx = 0.f;
#pragma unroll
        for (int a = 0; a < NA; a++) {
            float d = fmaxf(s_M[a * NP + p] * s_ra[a] * rp, 0.f) * 20.f;
            if (s_padf[a] == 0.f) { vv[a] = d; mx = fmaxf(mx, d); }
            else                  { vv[a] = -1.f; }
        }
        float ssum = 0.f;
#pragma unroll
        for (int a = 0; a < NA; a++) {
            float e = (vv[a] < 0.f) ? 0.f : __expf(vv[a] - mx);
            vv[a] = e; ssum += e;
        }
        const float rinv = 1.f / ssum;
#pragma unroll
        for (int a = 0; a < NA; a++) { vv[a] *= rinv; s_A2[a * NP + p] = vv[a]; }
        float z = 0.f;
#pragma unroll 1
        for (int b = 0; b < NA; b++) {
            const float* Gr = s_G + b * 32;
            float yb = 0.f;
#pragma unroll
            for (int a = 0; a < NA; a++) yb = fmaf(vv[a], Gr[a], yb);
            z = fmaf(yb, vv[b], z);
        }
        s_w[p] = rsqrtf(fmaxf(z, 1e-24f));
    }
    __syncthreads();

    // ---- Stage C: ||attend_patch_a||^2, patch staged through smem tiles ----
    {
        const int e4 = tid & 63, h = tid >> 6, a0 = h * 8;
        ull acc[8][2];
#pragma unroll
        for (int a = 0; a < 8; a++) { acc[a][0] = 0ull; acc[a][1] = 0ull; }

        for (int pt = 0; pt < 12; pt++) {
            const int p0 = pt * 16;
            // cooperative load of patch rows [p0, p0+16) x [0,256)
#pragma unroll
            for (int i2 = 0; i2 < 4; i2++) {
                int fid = tid + 256 * i2;
                int row = fid >> 6, col = (fid & 63) << 2;
                *(float4*)&s_tile[row * NE + col] =
                    *(const float4*)&pbase[(size_t)(p0 + row) * NE + col];
            }
            __syncthreads();
            stage_c_tile(s_tile, s_A1, acc, e4, a0, p0);
            __syncthreads();
        }
#pragma unroll
        for (int a = 0; a < 8; a++) {
            float2 f0 = upk(acc[a][0]), f1 = upk(acc[a][1]);
            float s = f0.x * f0.x + f0.y * f0.y + f1.x * f1.x + f1.y * f1.y;
#pragma unroll
            for (int o = 16; o > 0; o >>= 1) s += __shfl_xor_sync(~0u, s, o);
            if (lane == 0) s_red[wid * 8 + a] = s;
        }
    }
    __syncthreads();
    if (tid < NA) {
        const int hh = tid >> 3, al = tid & 7;
        float ss2 = s_red[(hh * 2) * 8 + al] + s_red[(hh * 2 + 1) * 8 + al];
        s_w2[tid] = (s_padf[tid] != 0.f) ? 0.f : rsqrtf(fmaxf(ss2, 1e-24f));
    }
    __syncthreads();

    // ---- c_a = sum_p attn2[a][p] * w_p ----
    for (int r = wid; r < NA; r += 8) {
        float cc = 0.f;
#pragma unroll
        for (int j = 0; j < 6; j++) {
            int p = lane + j * 32;
            cc = fmaf(s_A2[r * NP + p], s_w[p], cc);
        }
#pragma unroll
        for (int o = 16; o > 0; o >>= 1) cc += __shfl_xor_sync(~0u, cc, o);
        if (lane == 0) s_c[r] = cc;
    }
    __syncthreads();

    // ---- final: sim = sum_p d_p * (sum_a c_a M[a][p]) / (an*30) ----
    float fp = 0.f;
    if (tid < NP) {
        const int p = tid;
        float dp = 0.f, mp = 0.f;
#pragma unroll
        for (int a = 0; a < NA; a++) {
            dp = fmaf(s_A1[a * NP + p], s_w2[a], dp);
            mp = fmaf(s_c[a], s_M[a * NP + p], mp);
        }
        fp = dp * mp;
    }
#pragma unroll
    for (int o = 16; o > 0; o >>= 1) fp += __shfl_xor_sync(~0u, fp, o);
    if (lane == 0) s_red[wid] = fp;
    __syncthreads();
    if (tid == 0) {
        float tot = 0.f;
#pragma unroll
        for (int w2 = 0; w2 < 8; w2++) tot += s_red[w2];
        out_sim[t * NB + v] = tot / (s_an[0] * (float)NA);
    }
}

// ---------------------------------------------------------------------------
extern "C" void kernel_launch(void* const* d_in, const int* in_sizes, int n_in,
                              void* d_out, int out_size)
{
    const float* vf      = (const float*)d_in[0];
    const float* tf      = (const float*)d_in[1];
    const int*   mask    = (const int*)d_in[2];
    const int*   att_num = (const int*)d_in[3];
    const float* W_vis   = (const float*)d_in[4];
    const float* b_vis   = (const float*)d_in[5];
    const float* W_txt   = (const float*)d_in[6];
    const float* b_txt   = (const float*)d_in[7];
    const float* W_patch = (const float*)d_in[8];
    const float* b_patch = (const float*)d_in[9];
    const float* W_att   = (const float*)d_in[10];
    const float* b_att   = (const float*)d_in[11];
    float* out = (float*)d_out;

    void* p_patch = nullptr;
    void* p_att = nullptr;
    cudaGetSymbolAddress(&p_patch, g_patch);
    cudaGetSymbolAddress(&p_att, g_att);

    dim3 blk(256);
    // 1,2: projections
    proj_kernel<<<dim3(4, (NB * NP + 63) / 64), blk>>>(vf, W_patch, b_patch,
                                                       (float*)p_patch, NB * NP, SV, NP, 1);
    proj_kernel<<<dim3(4, (NB * NA + 63) / 64), blk>>>(tf, W_att, b_att,
                                                       (float*)p_att, NB * NA, ST, NA, 1);
    // 3: fused prep (transpose + norms + gram + means + cls)
    prep_kernel<<<4536, blk>>>(vf, tf, W_vis, b_vis, W_txt, b_txt, att_num, out);

    // 4: fused pair kernel (profiled launch)
    const int smem_bytes = SMEM_F * 4;
    cudaFuncSetAttribute(pair_kernel, cudaFuncAttributeMaxDynamicSharedMemorySize,
                         smem_bytes);
    pair_kernel<<<dim3(NB, NB), blk, smem_bytes>>>(mask, att_num, out + SIM_OFF);
}

// round 6
// speedup vs baseline: 1.8542x; 1.1761x over previous
#include <cuda_runtime.h>
#include <cstdint>
#include <math.h>

// Problem constants
#define NB 32     // batch
#define NP 192    // patches
#define NA 30     // attributes
#define NE 256    // embed dim
#define NK 768    // input feature dim
#define SV 193    // visual seq len
#define ST 31     // textual seq len

#define VE_OFF 0
#define TE_OFF 8192
#define PM_OFF 16384
#define AM_OFF 24576
#define SIM_OFF 32768

// Scratch
__device__ float g_patch[NB * NP * NE];    // [v][p][e]
__device__ float g_patchT[NB * NE * NP];   // [v][e][p]
__device__ float g_att[NB * NA * NE];
__device__ float g_rp[NB * NP];
__device__ float g_ra[NB * NA];
__device__ float g_G[NB * NA * 32];
__device__ float g_WT[4 * NK * NE];        // transposed weights [seg][k][n]

typedef unsigned long long ull;

__device__ __forceinline__ void fma2(ull& d, ull a, ull b) {
    asm("fma.rn.f32x2 %0, %1, %2, %3;" : "=l"(d) : "l"(a), "l"(b), "l"(d));
}
__device__ __forceinline__ ull pk2(float x, float y) {
    ull r; asm("mov.b64 %0, {%1,%2};" : "=l"(r) : "f"(x), "f"(y)); return r;
}
__device__ __forceinline__ float2 upk(ull v) {
    float2 r; asm("mov.b64 {%0,%1}, %2;" : "=f"(r.x), "=f"(r.y) : "l"(v)); return r;
}
__device__ __forceinline__ void cpa16(uint32_t s, const void* g) {
    asm volatile("cp.async.cg.shared.global [%0], [%1], 16;\n" :: "r"(s), "l"(g));
}
__device__ __forceinline__ void cpa_commit() {
    asm volatile("cp.async.commit_group;\n" ::: "memory");
}
template<int N>
__device__ __forceinline__ void cpa_wait() {
    asm volatile("cp.async.wait_group %0;\n" :: "n"(N) : "memory");
}

// ---------------------------------------------------------------------------
// Transpose the four weight matrices [256][768] -> g_WT[seg][768][256]
// grid (24, 8, 4), block 256
// ---------------------------------------------------------------------------
__global__ __launch_bounds__(256) void wt_kernel(
    const float* __restrict__ W0, const float* __restrict__ W1,
    const float* __restrict__ W2, const float* __restrict__ W3)
{
    __shared__ float ts[32][33];
    const int z = blockIdx.z;
    const float* W = (z == 0) ? W0 : (z == 1) ? W1 : (z == 2) ? W2 : W3;
    const int k0 = blockIdx.x * 32;   // col of W (0..767)
    const int n0 = blockIdx.y * 32;   // row of W (0..255)
    const int lane = threadIdx.x & 31, wid = threadIdx.x >> 5;
#pragma unroll
    for (int i = 0; i < 4; i++)
        ts[wid + 8 * i][lane] = W[(size_t)(n0 + wid + 8 * i) * NK + k0 + lane];
    __syncthreads();
    float* WT = g_WT + (size_t)z * NK * NE;
#pragma unroll
    for (int i = 0; i < 4; i++)
        WT[(size_t)(k0 + wid + 8 * i) * NE + n0 + lane] = ts[lane][wid + 8 * i];
}

// ---------------------------------------------------------------------------
// Merged projection GEMM, cp.async double-buffered.
// grid (4, 113): y<96 patch, y<111 att, y==111 vis cls, y==112 txt cls.
// 64m x 64n x 768k, k-chunk 32, microtile 4m x 4n (f32x2 over n).
// ---------------------------------------------------------------------------
__global__ __launch_bounds__(256) void proj2_kernel(
    const float* __restrict__ vf, const float* __restrict__ tf,
    const float* __restrict__ b_patch, const float* __restrict__ b_att,
    const float* __restrict__ b_vis, const float* __restrict__ b_txt,
    float* __restrict__ out)
{
    __shared__ float As[2][64 * 36];
    __shared__ float Bs[2][32 * 64];

    const int y = blockIdx.y;
    int seg, my;
    if (y < 96)       { seg = 0; my = y; }
    else if (y < 111) { seg = 1; my = y - 96; }
    else if (y == 111){ seg = 2; my = 0; }
    else              { seg = 3; my = 0; }

    const int M  = (seg == 0) ? NB * NP : (seg == 1) ? NB * NA : NB;
    const int S  = (seg == 0 || seg == 2) ? SV : ST;
    const int gs = (seg == 0) ? NP : (seg == 1) ? NA : 1;
    const int off= (seg <= 1) ? 1 : 0;
    const float* X = (seg == 0 || seg == 2) ? vf : tf;
    const float* bias = (seg == 0) ? b_patch : (seg == 1) ? b_att
                       : (seg == 2) ? b_vis : b_txt;
    float* obase;
    if (seg == 0) obase = g_patch;
    else if (seg == 1) obase = g_att;
    else if (seg == 2) obase = out + VE_OFF;
    else obase = out + TE_OFF;
    const float* WT = g_WT + (size_t)seg * NK * NE;

    const int col0 = blockIdx.x * 64;
    const int row0 = my * 64;
    const int tid = threadIdx.x;
    const int tm = tid >> 4, tn = tid & 15;

    // cp.async chunk mappings (2 A-chunks + 2 B-chunks per thread)
    const int c1 = tid + 256;
    const int ar0 = tid >> 3,  ac0 = (tid & 7) << 2;
    const int ar1 = c1 >> 3,   ac1 = (c1 & 7) << 2;
    int gr0 = row0 + ar0; if (gr0 >= M) gr0 = M - 1;
    int gr1 = row0 + ar1; if (gr1 >= M) gr1 = M - 1;
    const float* aS0 = X + (size_t)((gr0 / gs) * S + off + gr0 % gs) * NK + ac0;
    const float* aS1 = X + (size_t)((gr1 / gs) * S + off + gr1 % gs) * NK + ac1;
    const uint32_t aD0 = (ar0 * 36 + ac0) * 4;
    const uint32_t aD1 = (ar1 * 36 + ac1) * 4;
    const int bk0 = tid >> 4, bc0 = (tid & 15) << 2;
    const int bk1 = c1 >> 4,  bc1 = (c1 & 15) << 2;
    const float* bS0 = WT + (size_t)bk0 * NE + col0 + bc0;
    const float* bS1 = WT + (size_t)bk1 * NE + col0 + bc1;
    const uint32_t bD0 = (bk0 * 64 + bc0) * 4;
    const uint32_t bD1 = (bk1 * 64 + bc1) * 4;

    const uint32_t sA = (uint32_t)__cvta_generic_to_shared(&As[0][0]);
    const uint32_t sB = (uint32_t)__cvta_generic_to_shared(&Bs[0][0]);

    ull c2[4][2];
#pragma unroll
    for (int i = 0; i < 4; i++) { c2[i][0] = 0ull; c2[i][1] = 0ull; }

    // prologue: stage tile 0 into buffer 0
    {
        cpa16(sA + aD0, aS0);
        cpa16(sA + aD1, aS1);
        cpa16(sB + bD0, bS0);
        cpa16(sB + bD1, bS1);
        cpa_commit();
    }

    for (int it = 0; it < 24; it++) {
        const int cur = it & 1;
        if (it < 23) {
            const int nb = cur ^ 1;
            const uint32_t oA = sA + nb * (64 * 36 * 4);
            const uint32_t oB = sB + nb * (32 * 64 * 4);
            const int k0 = (it + 1) * 32;
            cpa16(oA + aD0, aS0 + k0);
            cpa16(oA + aD1, aS1 + k0);
            cpa16(oB + bD0, bS0 + (size_t)k0 * NE);
            cpa16(oB + bD1, bS1 + (size_t)k0 * NE);
            cpa_commit();
            cpa_wait<1>();
        } else {
            cpa_wait<0>();
        }
        __syncthreads();

        const float* A = As[cur];
        const float* B = Bs[cur];
#pragma unroll
        for (int q = 0; q < 8; q++) {
            float4 a[4];
#pragma unroll
            for (int i = 0; i < 4; i++)
                a[i] = *(const float4*)&A[(tm * 4 + i) * 36 + q * 4];
#pragma unroll
            for (int j = 0; j < 4; j++) {
                ulonglong2 bb = *(const ulonglong2*)&B[(q * 4 + j) * 64 + tn * 4];
#pragma unroll
                for (int i = 0; i < 4; i++) {
                    float av = (j == 0) ? a[i].x : (j == 1) ? a[i].y
                             : (j == 2) ? a[i].z : a[i].w;
                    ull d = pk2(av, av);
                    fma2(c2[i][0], d, bb.x);
                    fma2(c2[i][1], d, bb.y);
                }
            }
        }
        __syncthreads();
    }

    const float4 b4 = *(const float4*)&bias[col0 + tn * 4];
#pragma unroll
    for (int i = 0; i < 4; i++) {
        int r = row0 + tm * 4 + i;
        if (r < M) {
            float2 lo = upk(c2[i][0]), hi = upk(c2[i][1]);
            float4 o;
            o.x = lo.x + b4.x; o.y = lo.y + b4.y;
            o.z = hi.x + b4.z; o.w = hi.y + b4.w;
            *(float4*)&obase[(size_t)r * NE + col0 + tn * 4] = o;
        }
    }
}

// ---------------------------------------------------------------------------
// Fused prep kernel: transpose | norms | gram | means
// grid x ranges: [0,1536) transpose, [1536,2424) norm, [2424,2456) gram,
//                [2456,2488) mean
// ---------------------------------------------------------------------------
__global__ __launch_bounds__(256) void prep_kernel(
    const int* __restrict__ att_nums, float* __restrict__ out)
{
    __shared__ float sbuf[NA * NE];
    const int r = blockIdx.x;
    const int tid = threadIdx.x;
    const int lane = tid & 31, wid = tid >> 5;

    if (r < 1536) {
        float (*ts)[33] = (float (*)[33])sbuf;
        const int v = r / 48, rem = r % 48;
        const int e0 = (rem / 6) * 32, p0 = (rem % 6) * 32;
        const float* src = g_patch + (size_t)v * NP * NE;
        float* dst = g_patchT + (size_t)v * NE * NP;
#pragma unroll
        for (int k = 0; k < 4; k++)
            ts[wid + 8 * k][lane] = src[(size_t)(p0 + wid + 8 * k) * NE + e0 + lane];
        __syncthreads();
#pragma unroll
        for (int k = 0; k < 4; k++)
            dst[(size_t)(e0 + wid + 8 * k) * NP + p0 + lane] = ts[lane][wid + 8 * k];
    } else if (r < 2424) {
        const int w = (r - 1536) * 8 + wid;
        if (w >= NB * NP + NB * NA) return;
        const float* row;
        float* dst;
        if (w < NB * NP) { row = g_patch + (size_t)w * NE; dst = &g_rp[w]; }
        else { row = g_att + (size_t)(w - NB * NP) * NE; dst = &g_ra[w - NB * NP]; }
        float4 x0 = *(const float4*)&row[lane * 4];
        float4 x1 = *(const float4*)&row[128 + lane * 4];
        float ss = x0.x * x0.x + x0.y * x0.y + x0.z * x0.z + x0.w * x0.w
                 + x1.x * x1.x + x1.y * x1.y + x1.z * x1.z + x1.w * x1.w;
#pragma unroll
        for (int o = 16; o > 0; o >>= 1) ss += __shfl_xor_sync(~0u, ss, o);
        if (lane == 0) *dst = rsqrtf(fmaxf(ss, 1e-24f));
    } else if (r < 2456) {
        const int t = r - 2424;
        const float* ap = g_att + (size_t)t * NA * NE;
        for (int i = tid; i < NA * NE; i += 256) sbuf[i] = ap[i];
        __syncthreads();
        for (int idx = tid; idx < NA * NA; idx += 256) {
            int a = idx / NA, b = idx % NA;
            const float* ra = sbuf + a * NE;
            const float* rb = sbuf + b * NE;
            float acc = 0.f;
#pragma unroll 4
            for (int e = 0; e < NE; e += 4) {
                float4 x = *(float4*)&ra[e];
                float4 y = *(float4*)&rb[e];
                acc += x.x * y.x + x.y * y.y + x.z * y.z + x.w * y.w;
            }
            g_G[t * NA * 32 + a * 32 + b] = acc;
        }
    } else {
        const int b = r - 2456;
        const int e = tid;
        float pm = 0.f;
        const float* pb = g_patch + (size_t)b * NP * NE + e;
#pragma unroll 4
        for (int p = 0; p < NP; p++) pm += pb[(size_t)p * NE];
        out[PM_OFF + b * NE + e] = pm / (float)NP;
        float am = 0.f;
        const float* ab = g_att + (size_t)b * NA * NE + e;
#pragma unroll
        for (int a = 0; a < NA; a++) am += ab[(size_t)a * NE];
        out[AM_OFF + b * NE + e] = am / (float)att_nums[b];
    }
}

// ---------------------------------------------------------------------------
// Pair kernel smem layout (floats). Total 28289 fl = 113156 B -> 2 CTAs/SM.
// ---------------------------------------------------------------------------
#define SA_ATT  0          /* 8192 : att padded to 32 rows (zeros) */
#define SA_M    8192       /* 6144 : M [32][192] */
#define SA_A1   14336      /* 6144 : attn1 padded to 32 rows (rows 30,31 zero) */
#define SA_TILE 20480      /* 6272 : stage A: 2x16x196; stage C: 16x256 */
#define SA_G    26752      /* 960 */
#define SA_RA   27712      /* 32 */
#define SA_RP   27744      /* 192 */
#define SA_PADF 27936      /* 32 */
#define SA_W    27968      /* 192 */
#define SA_W2   28160      /* 32 */
#define SA_C    28192      /* 32 */
#define SA_RED  28224      /* 64 */
#define SA_AN   28288      /* 1 */
#define SMEM_F  28289
#define TILE_LD 196

// Stage C per-tile compute: 16 p-rows from s_ctile [16][256], 8 a's.
__device__ __forceinline__ void stage_c_tile(const float* __restrict__ s_ctile,
                                             const float* __restrict__ s_A1,
                                             ull (&acc)[8][2], int e4, int a0, int p0)
{
#pragma unroll
    for (int pp = 0; pp < 16; pp += 4) {
        ulonglong2 u0 = *(const ulonglong2*)&s_ctile[(pp + 0) * NE + e4 * 4];
        ulonglong2 u1 = *(const ulonglong2*)&s_ctile[(pp + 1) * NE + e4 * 4];
        ulonglong2 u2 = *(const ulonglong2*)&s_ctile[(pp + 2) * NE + e4 * 4];
        ulonglong2 u3 = *(const ulonglong2*)&s_ctile[(pp + 3) * NE + e4 * 4];
#pragma unroll
        for (int a = 0; a < 8; a++) {
            float4 q = *(const float4*)&s_A1[(a0 + a) * NP + p0 + pp];
            ull w0 = pk2(q.x, q.x), w1 = pk2(q.y, q.y);
            ull w2 = pk2(q.z, q.z), w3 = pk2(q.w, q.w);
            fma2(acc[a][0], w0, u0.x); fma2(acc[a][1], w0, u0.y);
            fma2(acc[a][0], w1, u1.x); fma2(acc[a][1], w1, u1.y);
            fma2(acc[a][0], w2, u2.x); fma2(acc[a][1], w2, u2.y);
            fma2(acc[a][0], w3, u3.x); fma2(acc[a][1], w3, u3.y);
        }
    }
}

// ---------------------------------------------------------------------------
// Fused per-(t,v) pair kernel. 256 threads, 113 KB smem, 2 CTAs/SM.
// ---------------------------------------------------------------------------
__global__ __launch_bounds__(256, 2) void pair_kernel(const int* __restrict__ mask,
                                                      const int* __restrict__ att_nums,
                                                      float* __restrict__ out_sim)
{
    extern __shared__ float sm[];
    const int v = blockIdx.x, t = blockIdx.y;
    const int tid = threadIdx.x, lane = tid & 31, wid = tid >> 5;

    float* s_att  = sm + SA_ATT;
    float* s_M    = sm + SA_M;
    float* s_A1   = sm + SA_A1;
    float* s_A2   = sm + SA_ATT;    // alias: att dead after stage A
    float* s_tile = sm + SA_TILE;
    float* s_G    = sm + SA_G;
    float* s_ra   = sm + SA_RA;
    float* s_rp   = sm + SA_RP;
    float* s_padf = sm + SA_PADF;
    float* s_w    = sm + SA_W;
    float* s_w2   = sm + SA_W2;
    float* s_c    = sm + SA_C;
    float* s_red  = sm + SA_RED;
    float* s_an   = sm + SA_AN;

    // ---- preload ----
    const float* attp = g_att + (size_t)t * NA * NE;
    for (int i = tid; i < 32 * NE; i += 256)
        s_att[i] = (i < NA * NE) ? attp[i] : 0.f;
    const float* gGp = g_G + t * NA * 32;
    for (int i = tid; i < NA * 32; i += 256) s_G[i] = gGp[i];
    for (int i = tid; i < 2 * NP; i += 256) s_A1[NA * NP + i] = 0.f;
    if (tid < NA) {
        s_ra[tid] = g_ra[t * NA + tid];
        s_padf[tid] = (mask[t * NA + tid] != 0) ? 1.f : 0.f;
    }
    if (tid < NP) s_rp[tid] = g_rp[v * NP + tid];
    if (tid == 0) s_an[0] = (float)att_nums[t];
    __syncthreads();

    const float* pbase = g_patch + (size_t)v * NP * NE;
    const float* ptv   = g_patchT + (size_t)v * NE * NP;

    // ---- Stage A: M[a][p] = att_a . patch_p. 8a x 6p microtile, e-split 2 ----
    {
        const int eg = tid >> 7;          // e-half
        const int g  = tid & 127;
        const int at = g >> 5;            // warp-within-group = a-tile
        const int pt = g & 31;
        const int a0 = at * 8, p0 = pt * 6;
        float* my_tile = s_tile + eg * (16 * TILE_LD);

        ull acc[8][3];
#pragma unroll
        for (int a = 0; a < 8; a++) { acc[a][0] = acc[a][1] = acc[a][2] = 0ull; }

        for (int c = 0; c < 8; c++) {
            const int e0 = eg * 128 + c * 16;
#pragma unroll
            for (int i = 0; i < 6; i++) {
                int fid = g + 128 * i;
                int row = fid / 48, col = (fid % 48) * 4;
                *(float4*)&my_tile[row * TILE_LD + col] =
                    *(const float4*)&ptv[(size_t)(e0 + row) * NP + col];
            }
            __syncthreads();
#pragma unroll
            for (int e4 = 0; e4 < 16; e4 += 4) {
                float4 av[8];
#pragma unroll
                for (int a = 0; a < 8; a++)
                    av[a] = *(const float4*)&s_att[(a0 + a) * NE + e0 + e4];
#pragma unroll
                for (int j = 0; j < 4; j++) {
                    const float* tr = &my_tile[(e4 + j) * TILE_LD + p0];
                    ull p01 = *(const ull*)&tr[0];
                    ull p23 = *(const ull*)&tr[2];
                    ull p45 = *(const ull*)&tr[4];
#pragma unroll
                    for (int a = 0; a < 8; a++) {
                        float aval = (j == 0) ? av[a].x : (j == 1) ? av[a].y
                                   : (j == 2) ? av[a].z : av[a].w;
                        ull ad = pk2(aval, aval);
                        fma2(acc[a][0], ad, p01);
                        fma2(acc[a][1], ad, p23);
                        fma2(acc[a][2], ad, p45);
                    }
                }
            }
            __syncthreads();
        }
        if (eg == 1) {
#pragma unroll
            for (int a = 0; a < 8; a++)
#pragma unroll
                for (int jj = 0; jj < 3; jj++) {
                    float2 f = upk(acc[a][jj]);
                    *(float2*)&s_M[(a0 + a) * NP + p0 + 2 * jj] = f;
                }
        }
        __syncthreads();
        if (eg == 0) {
#pragma unroll
            for (int a = 0; a < 8; a++)
#pragma unroll
                for (int jj = 0; jj < 3; jj++) {
                    float2 f = upk(acc[a][jj]);
                    float2 o = *(float2*)&s_M[(a0 + a) * NP + p0 + 2 * jj];
                    o.x += f.x; o.y += f.y;
                    *(float2*)&s_M[(a0 + a) * NP + p0 + 2 * jj] = o;
                }
        }
        __syncthreads();
    }

    // ---- attn1: softmax over p of D = relu(M*ra*rp)*20 (warp per row) ----
    for (int r = wid; r < NA; r += 8) {
        const float ra = s_ra[r];
        float x[6];
        float mx = 0.f;
#pragma unroll
        for (int j = 0; j < 6; j++) {
            int p = lane + j * 32;
            float d = fmaxf(s_M[r * NP + p] * ra * s_rp[p], 0.f) * 20.f;
            x[j] = d; mx = fmaxf(mx, d);
        }
#pragma unroll
        for (int o = 16; o > 0; o >>= 1) mx = fmaxf(mx, __shfl_xor_sync(~0u, mx, o));
        float ssum = 0.f;
#pragma unroll
        for (int j = 0; j < 6; j++) { x[j] = __expf(x[j] - mx); ssum += x[j]; }
#pragma unroll
        for (int o = 16; o > 0; o >>= 1) ssum += __shfl_xor_sync(~0u, ssum, o);
        const float rinv = 1.f / ssum;
#pragma unroll
        for (int j = 0; j < 6; j++) s_A1[r * NP + lane + j * 32] = x[j] * rinv;
    }

    // ---- attn2 (masked softmax over a) + Gram quadratic -> w_p ----
    if (tid < NP) {
        const int p = tid;
        const float rp = s_rp[p];
        float vv[NA];
        float mx = 0.f;
#pragma unroll
        for (int a = 0; a < NA; a++) {
            float d = fmaxf(s_M[a * NP + p] * s_ra[a] * rp, 0.f) * 20.f;
            if (s_padf[a] == 0.f) { vv[a] = d; mx = fmaxf(mx, d); }
            else                  { vv[a] = -1.f; }
        }
        float ssum = 0.f;
#pragma unroll
        for (int a = 0; a < NA; a++) {
            float e = (vv[a] < 0.f) ? 0.f : __expf(vv[a] - mx);
            vv[a] = e; ssum += e;
        }
        const float rinv = 1.f / ssum;
#pragma unroll
        for (int a = 0; a < NA; a++) { vv[a] *= rinv; s_A2[a * NP + p] = vv[a]; }
        float z = 0.f;
#pragma unroll 1
        for (int b = 0; b < NA; b++) {
            const float* Gr = s_G + b * 32;
            float yb = 0.f;
#pragma unroll
            for (int a = 0; a < NA; a++) yb = fmaf(vv[a], Gr[a], yb);
            z = fmaf(yb, vv[b], z);
        }
        s_w[p] = rsqrtf(fmaxf(z, 1e-24f));
    }
    __syncthreads();

    // ---- Stage C: ||attend_patch_a||^2, patch staged through smem tiles ----
    {
        const int e4 = tid & 63, h = tid >> 6, a0 = h * 8;
        ull acc[8][2];
#pragma unroll
        for (int a = 0; a < 8; a++) { acc[a][0] = 0ull; acc[a][1] = 0ull; }

        for (int pt = 0; pt < 12; pt++) {
            const int p0 = pt * 16;
#pragma unroll
            for (int i2 = 0; i2 < 4; i2++) {
                int fid = tid + 256 * i2;
                int row = fid >> 6, col = (fid & 63) << 2;
                *(float4*)&s_tile[row * NE + col] =
                    *(const float4*)&pbase[(size_t)(p0 + row) * NE + col];
            }
            __syncthreads();
            stage_c_tile(s_tile, s_A1, acc, e4, a0, p0);
            __syncthreads();
        }
#pragma unroll
        for (int a = 0; a < 8; a++) {
            float2 f0 = upk(acc[a][0]), f1 = upk(acc[a][1]);
            float s = f0.x * f0.x + f0.y * f0.y + f1.x * f1.x + f1.y * f1.y;
#pragma unroll
            for (int o = 16; o > 0; o >>= 1) s += __shfl_xor_sync(~0u, s, o);
            if (lane == 0) s_red[wid * 8 + a] = s;
        }
    }
    __syncthreads();
    if (tid < NA) {
        const int hh = tid >> 3, al = tid & 7;
        float ss2 = s_red[(hh * 2) * 8 + al] + s_red[(hh * 2 + 1) * 8 + al];
        s_w2[tid] = (s_padf[tid] != 0.f) ? 0.f : rsqrtf(fmaxf(ss2, 1e-24f));
    }
    __syncthreads();

    // ---- c_a = sum_p attn2[a][p] * w_p ----
    for (int r = wid; r < NA; r += 8) {
        float cc = 0.f;
#pragma unroll
        for (int j = 0; j < 6; j++) {
            int p = lane + j * 32;
            cc = fmaf(s_A2[r * NP + p], s_w[p], cc);
        }
#pragma unroll
        for (int o = 16; o > 0; o >>= 1) cc += __shfl_xor_sync(~0u, cc, o);
        if (lane == 0) s_c[r] = cc;
    }
    __syncthreads();

    // ---- final: sim = sum_p d_p * (sum_a c_a M[a][p]) / (an*30) ----
    float fp = 0.f;
    if (tid < NP) {
        const int p = tid;
        float dp = 0.f, mp = 0.f;
#pragma unroll
        for (int a = 0; a < NA; a++) {
            dp = fmaf(s_A1[a * NP + p], s_w2[a], dp);
            mp = fmaf(s_c[a], s_M[a * NP + p], mp);
        }
        fp = dp * mp;
    }
#pragma unroll
    for (int o = 16; o > 0; o >>= 1) fp += __shfl_xor_sync(~0u, fp, o);
    if (lane == 0) s_red[wid] = fp;
    __syncthreads();
    if (tid == 0) {
        float tot = 0.f;
#pragma unroll
        for (int w2 = 0; w2 < 8; w2++) tot += s_red[w2];
        out_sim[t * NB + v] = tot / (s_an[0] * (float)NA);
    }
}

// ---------------------------------------------------------------------------
extern "C" void kernel_launch(void* const* d_in, const int* in_sizes, int n_in,
                              void* d_out, int out_size)
{
    const float* vf      = (const float*)d_in[0];
    const float* tf      = (const float*)d_in[1];
    const int*   mask    = (const int*)d_in[2];
    const int*   att_num = (const int*)d_in[3];
    const float* W_vis   = (const float*)d_in[4];
    const float* b_vis   = (const float*)d_in[5];
    const float* W_txt   = (const float*)d_in[6];
    const float* b_txt   = (const float*)d_in[7];
    const float* W_patch = (const float*)d_in[8];
    const float* b_patch = (const float*)d_in[9];
    const float* W_att   = (const float*)d_in[10];
    const float* b_att   = (const float*)d_in[11];
    float* out = (float*)d_out;

    dim3 blk(256);
    // 1: weight transposes (seg order: patch, att, vis, txt)
    wt_kernel<<<dim3(24, 8, 4), blk>>>(W_patch, W_att, W_vis, W_txt);
    // 2: merged projections (patch + att + both cls), cp.async pipelined
    proj2_kernel<<<dim3(4, 113), blk>>>(vf, tf, b_patch, b_att, b_vis, b_txt, out);
    // 3: fused prep (transpose + norms + gram + means)
    prep_kernel<<<2488, blk>>>(att_num, out);
    // 4: fused pair kernel
    const int smem_bytes = SMEM_F * 4;
    cudaFuncSetAttribute(pair_kernel, cudaFuncAttributeMaxDynamicSharedMemorySize,
                         smem_bytes);
    pair_kernel<<<dim3(NB, NB), blk, smem_bytes>>>(mask, att_num, out + SIM_OFF);
}